// round 8
// baseline (speedup 1.0000x reference)
#include <cuda_runtime.h>
#include <cuda_bf16.h>
#include <math.h>
#include <stdint.h>

#define B_   16
#define T_   256
#define V_   18000
#define NS_  30
#define L_   10
#define G_   3
#define H_   400
#define N_   480      // NS_*B_
#define H3_  1200
#define KDIM 400
#define KP   448      // K padded to 7*64 for bf16 MMA
#define NKC  7        // K chunks of 64

// ---------------- scratch (static __device__, allowed) ----------------
__device__ float d_dec[L_*N_*H_];
__device__ float d_gi[L_*N_*H3_];
__device__ float d_gh[N_*H3_];
__device__ float d_h[2][N_*H_];
__device__ float d_prob[N_*T_];
__device__ float d_sw[N_];
__device__ float d_rowsum[N_];
__device__ float d_logits[(size_t)N_*V_];
__device__ __nv_bfloat16 d_emb_bf[(size_t)V_*KP];   // padded bf16 emb
__device__ __nv_bfloat16 d_h_bf[512*KP];            // padded bf16 h (pad stays zero)

// ---------------- emb -> padded bf16 (once per launch) ----------------
__global__ void k_cvt_emb(const float* __restrict__ emb)
{
    size_t i = (size_t)blockIdx.x * 256 + threadIdx.x;
    if (i >= (size_t)V_ * KP) return;
    int c = (int)(i % KP);
    int n = (int)(i / KP);
    float v = (c < H_) ? emb[(size_t)n * H_ + c] : 0.f;
    d_emb_bf[i] = __float2bfloat16(v);
}

// ================= mma.sync helpers (family-portable, sm_80+) =================
__device__ __forceinline__ void ldmat4(uint32_t* r, uint32_t addr)
{
    asm volatile("ldmatrix.sync.aligned.m8n8.x4.shared.b16 {%0,%1,%2,%3}, [%4];"
                 : "=r"(r[0]), "=r"(r[1]), "=r"(r[2]), "=r"(r[3]) : "r"(addr));
}
__device__ __forceinline__ void mma_bf16(float* d, const uint32_t* a, uint32_t b0, uint32_t b1)
{
    asm volatile(
        "mma.sync.aligned.m16n8k16.row.col.f32.bf16.bf16.f32 "
        "{%0,%1,%2,%3}, {%4,%5,%6,%7}, {%8,%9}, {%0,%1,%2,%3};"
        : "+f"(d[0]), "+f"(d[1]), "+f"(d[2]), "+f"(d[3])
        : "r"(a[0]), "r"(a[1]), "r"(a[2]), "r"(a[3]), "r"(b0), "r"(b1));
}

// ---------------- vocab GEMM via mma.sync ----------
// C(480x18000) = h_bf(512x448) @ emb_bf(18000x448)^T; epilogue exp + rowsum.
__global__ void __launch_bounds__(256) k_vocab_mma(float* __restrict__ logits)
{
    __shared__ alignas(128) uint8_t As[16384];
    __shared__ alignas(128) uint8_t Bs[16384];
    __shared__ float srow[128];

    const int tid  = threadIdx.x;
    const int lane = tid & 31;
    const int wid  = tid >> 5;
    const int wm   = (wid & 1) * 64;
    const int wn   = (wid >> 1) * 32;
    const int m0   = blockIdx.y * 128;
    const int n0   = blockIdx.x * 128;
    const uint32_t aBase = (uint32_t)__cvta_generic_to_shared(As);
    const uint32_t bBase = (uint32_t)__cvta_generic_to_shared(Bs);

    float acc[4][4][4];
    #pragma unroll
    for (int i = 0; i < 4; i++)
        #pragma unroll
        for (int j = 0; j < 4; j++)
            #pragma unroll
            for (int q = 0; q < 4; q++) acc[i][j][q] = 0.f;

    for (int kc = 0; kc < NKC; kc++) {
        __syncthreads();
        #pragma unroll
        for (int x = tid; x < 1024; x += 256) {
            int r = x >> 3, c = x & 7;
            uint4 v = *(const uint4*)((const char*)d_h_bf + ((size_t)(m0 + r) * KP + kc * 64) * 2 + c * 16);
            uint32_t off = (uint32_t)(r * 128 + c * 16);
            *(uint4*)(As + (off ^ ((off >> 3) & 0x70))) = v;
        }
        #pragma unroll
        for (int x = tid; x < 1024; x += 256) {
            int r = x >> 3, c = x & 7;
            int gn = n0 + r;
            uint4 v = make_uint4(0u, 0u, 0u, 0u);
            if (gn < V_)
                v = *(const uint4*)((const char*)d_emb_bf + ((size_t)gn * KP + kc * 64) * 2 + c * 16);
            uint32_t off = (uint32_t)(r * 128 + c * 16);
            *(uint4*)(Bs + (off ^ ((off >> 3) & 0x70))) = v;
        }
        __syncthreads();

        #pragma unroll
        for (int ks = 0; ks < 4; ks++) {
            uint32_t af[4][4];
            #pragma unroll
            for (int mt = 0; mt < 4; mt++) {
                int row  = wm + mt * 16 + (lane & 7) + ((lane & 8) ? 8 : 0);
                int koff = ks * 32 + ((lane & 16) ? 16 : 0);
                uint32_t off = (uint32_t)(row * 128 + koff);
                ldmat4(af[mt], aBase + (off ^ ((off >> 3) & 0x70)));
            }
            uint32_t bfr[2][4];
            #pragma unroll
            for (int hh = 0; hh < 2; hh++) {
                int row  = wn + hh * 16 + (lane & 7) + ((lane & 16) ? 8 : 0);
                int koff = ks * 32 + ((lane & 8) ? 16 : 0);
                uint32_t off = (uint32_t)(row * 128 + koff);
                ldmat4(bfr[hh], bBase + (off ^ ((off >> 3) & 0x70)));
            }
            #pragma unroll
            for (int mt = 0; mt < 4; mt++)
                #pragma unroll
                for (int nt = 0; nt < 4; nt++)
                    mma_bf16(acc[mt][nt], af[mt],
                             bfr[nt >> 1][(nt & 1) * 2 + 0],
                             bfr[nt >> 1][(nt & 1) * 2 + 1]);
        }
    }

    if (tid < 128) srow[tid] = 0.f;
    __syncthreads();
    #pragma unroll
    for (int mt = 0; mt < 4; mt++) {
        int rlo = wm + mt * 16 + (lane >> 2);
        int rhi = rlo + 8;
        int gmlo = m0 + rlo, gmhi = m0 + rhi;
        float slo = 0.f, shi = 0.f;
        #pragma unroll
        for (int nt = 0; nt < 4; nt++) {
            int gcol = n0 + wn + nt * 8 + 2 * (lane & 3);
            if (gcol < V_) {
                if (gmlo < N_) {
                    float e0 = __expf(acc[mt][nt][0]);
                    float e1 = __expf(acc[mt][nt][1]);
                    *(float2*)&logits[(size_t)gmlo * V_ + gcol] = make_float2(e0, e1);
                    slo += e0 + e1;
                }
                if (gmhi < N_) {
                    float e2 = __expf(acc[mt][nt][2]);
                    float e3 = __expf(acc[mt][nt][3]);
                    *(float2*)&logits[(size_t)gmhi * V_ + gcol] = make_float2(e2, e3);
                    shi += e2 + e3;
                }
            }
        }
        slo += __shfl_xor_sync(0xffffffffu, slo, 1);
        slo += __shfl_xor_sync(0xffffffffu, slo, 2);
        shi += __shfl_xor_sync(0xffffffffu, shi, 1);
        shi += __shfl_xor_sync(0xffffffffu, shi, 2);
        if ((lane & 3) == 0) {
            if (gmlo < N_) atomicAdd(&srow[rlo], slo);
            if (gmhi < N_) atomicAdd(&srow[rhi], shi);
        }
    }
    __syncthreads();
    if (tid < 128 && m0 + tid < N_) atomicAdd(&d_rowsum[m0 + tid], srow[tid]);
}

// ---------------- K0: build decoder inputs + h0 ----------------
__global__ void k_prep(const float* __restrict__ enc_hidden,
                       const float* __restrict__ emb,
                       const float* __restrict__ slot_emb,
                       const int*   __restrict__ domain_idx,
                       const int*   __restrict__ slotname_idx,
                       const int*   __restrict__ targets)
{
    int n  = blockIdx.x;
    int wi = blockIdx.y;
    int h  = threadIdx.x;
    int slot = n / B_, b = n % B_;
    float v;
    if (wi == 0) {
        v = slot_emb[domain_idx[slot]*H_ + h] + slot_emb[slotname_idx[slot]*H_ + h];
        d_h[0][n*H_ + h] = enc_hidden[b*H_ + h];
    } else {
        int tok = targets[(b*NS_ + slot)*L_ + (wi-1)];
        v = emb[(size_t)tok*H_ + h];
    }
    d_dec[(size_t)(wi*N_ + n)*H_ + h] = v;
}

// ---------------- fp32 SIMT GEMM 128x128 (big gi GEMM) ----------------
__global__ void k_gemm_abt(const float* __restrict__ A, const float* __restrict__ Bm,
                           float* __restrict__ C, int M, int N,
                           const float* __restrict__ bias)
{
    __shared__ alignas(16) float As[8][128];
    __shared__ alignas(16) float Bs[8][128];
    const int tid = threadIdx.x;
    const int m0 = blockIdx.y * 128;
    const int n0 = blockIdx.x * 128;
    const int tm = (tid & 15) * 8;
    const int tn = (tid >> 4) * 8;

    float acc[8][8];
    #pragma unroll
    for (int i = 0; i < 8; i++)
        #pragma unroll
        for (int j = 0; j < 8; j++) acc[i][j] = 0.f;

    const int lr = tid >> 1;
    const int lk = (tid & 1) * 4;

    for (int k0 = 0; k0 < KDIM; k0 += 8) {
        float4 av = make_float4(0.f,0.f,0.f,0.f);
        float4 bv = make_float4(0.f,0.f,0.f,0.f);
        if (m0 + lr < M) av = *reinterpret_cast<const float4*>(A + (size_t)(m0+lr)*KDIM + k0 + lk);
        if (n0 + lr < N) bv = *reinterpret_cast<const float4*>(Bm + (size_t)(n0+lr)*KDIM + k0 + lk);
        __syncthreads();
        As[lk+0][lr]=av.x; As[lk+1][lr]=av.y; As[lk+2][lr]=av.z; As[lk+3][lr]=av.w;
        Bs[lk+0][lr]=bv.x; Bs[lk+1][lr]=bv.y; Bs[lk+2][lr]=bv.z; Bs[lk+3][lr]=bv.w;
        __syncthreads();
        #pragma unroll
        for (int kk = 0; kk < 8; kk++) {
            float4 a0 = *reinterpret_cast<float4*>(&As[kk][tm]);
            float4 a1 = *reinterpret_cast<float4*>(&As[kk][tm+4]);
            float4 b0 = *reinterpret_cast<float4*>(&Bs[kk][tn]);
            float4 b1 = *reinterpret_cast<float4*>(&Bs[kk][tn+4]);
            float a[8] = {a0.x,a0.y,a0.z,a0.w,a1.x,a1.y,a1.z,a1.w};
            float b[8] = {b0.x,b0.y,b0.z,b0.w,b1.x,b1.y,b1.z,b1.w};
            #pragma unroll
            for (int i = 0; i < 8; i++)
                #pragma unroll
                for (int j = 0; j < 8; j++)
                    acc[i][j] += a[i] * b[j];
        }
    }
    #pragma unroll
    for (int i = 0; i < 8; i++) {
        int m = m0 + tm + i;
        if (m < M) {
            #pragma unroll
            for (int j = 0; j < 8; j++) {
                int n = n0 + tn + j;
                if (n < N) {
                    float v = acc[i][j];
                    if (bias) v += bias[n];
                    C[(size_t)m*N + n] = v;
                }
            }
        }
    }
}

// ---------------- fp32 SIMT GEMM 64x64 (per-step gh GEMM: more CTAs) --------
__global__ void __launch_bounds__(128) k_gemm64(const float* __restrict__ A,
                                                const float* __restrict__ Bm,
                                                float* __restrict__ C, int M, int N,
                                                const float* __restrict__ bias)
{
    __shared__ alignas(16) float As[16][64];
    __shared__ alignas(16) float Bs[16][64];
    const int tid = threadIdx.x;
    const int m0 = blockIdx.y * 64;
    const int n0 = blockIdx.x * 64;
    const int tm = (tid & 15) * 4;
    const int tn = (tid >> 4) * 8;

    float acc[4][8];
    #pragma unroll
    for (int i = 0; i < 4; i++)
        #pragma unroll
        for (int j = 0; j < 8; j++) acc[i][j] = 0.f;

    for (int k0 = 0; k0 < KDIM; k0 += 16) {
        __syncthreads();
        #pragma unroll
        for (int i = tid; i < 256; i += 128) {
            int r = i >> 2, lk = (i & 3) * 4;
            float4 v = make_float4(0.f,0.f,0.f,0.f);
            if (m0 + r < M) v = *(const float4*)(A + (size_t)(m0+r)*KDIM + k0 + lk);
            As[lk+0][r]=v.x; As[lk+1][r]=v.y; As[lk+2][r]=v.z; As[lk+3][r]=v.w;
        }
        #pragma unroll
        for (int i = tid; i < 256; i += 128) {
            int r = i >> 2, lk = (i & 3) * 4;
            float4 v = make_float4(0.f,0.f,0.f,0.f);
            if (n0 + r < N) v = *(const float4*)(Bm + (size_t)(n0+r)*KDIM + k0 + lk);
            Bs[lk+0][r]=v.x; Bs[lk+1][r]=v.y; Bs[lk+2][r]=v.z; Bs[lk+3][r]=v.w;
        }
        __syncthreads();
        #pragma unroll
        for (int kk = 0; kk < 16; kk++) {
            float4 a4 = *(float4*)&As[kk][tm];
            float4 b0 = *(float4*)&Bs[kk][tn];
            float4 b1 = *(float4*)&Bs[kk][tn+4];
            float a[4] = {a4.x, a4.y, a4.z, a4.w};
            float b[8] = {b0.x,b0.y,b0.z,b0.w,b1.x,b1.y,b1.z,b1.w};
            #pragma unroll
            for (int i = 0; i < 4; i++)
                #pragma unroll
                for (int j = 0; j < 8; j++)
                    acc[i][j] += a[i] * b[j];
        }
    }
    #pragma unroll
    for (int i = 0; i < 4; i++) {
        int m = m0 + tm + i;
        if (m < M) {
            #pragma unroll
            for (int j = 0; j < 8; j++) {
                int n = n0 + tn + j;
                if (n < N) {
                    float v = acc[i][j];
                    if (bias) v += bias[n];
                    C[(size_t)m*N + n] = v;
                }
            }
        }
    }
}

// ---------------- fused step kernel: GRU + scores + softmax + ctx + switch ----
// block per row n (480), 512 threads.
__global__ void __launch_bounds__(512) k_step(int wi, int pin, int pout,
                         const float* __restrict__ enc, const int* __restrict__ lens,
                         const float* __restrict__ w_ratio, const float* __restrict__ b_ratio,
                         const float* __restrict__ w_gate,  const float* __restrict__ b_gate,
                         float* __restrict__ out)
{
    __shared__ alignas(16) float hsh[H_];
    __shared__ alignas(16) float psh[T_];
    __shared__ float red[16];
    const int n = blockIdx.x;
    const int tid = threadIdx.x;
    const int lane = tid & 31;
    const int wrp = tid >> 5;
    const int b = n % B_;

    // phase 1: GRU combine
    float hv = 0.f;
    if (tid < H_) {
        const float* gi = &d_gi[(size_t)(wi*N_ + n)*H3_];
        const float* gh = &d_gh[(size_t)n*H3_];
        float hp = d_h[pin][n*H_ + tid];
        float r  = 1.f / (1.f + expf(-(gi[tid]       + gh[tid])));
        float z  = 1.f / (1.f + expf(-(gi[H_+tid]    + gh[H_+tid])));
        float nn = tanhf(gi[2*H_+tid] + r * gh[2*H_+tid]);
        hv = (1.f - z) * nn + z * hp;
        d_h[pout][n*H_ + tid] = hv;
        d_h_bf[n*KP + tid] = __float2bfloat16(hv);
        hsh[tid] = hv;
    }
    if (tid == 0) d_rowsum[n] = 0.f;
    __syncthreads();

    // phase 2: attention scores (threads 0..255 each own one t)
    float sc = -1e30f;
    if (tid < T_) {
        const float4* e4 = (const float4*)(enc + ((size_t)b*T_ + tid)*H_);
        const float4* h4 = (const float4*)hsh;
        float s0 = 0.f, s1 = 0.f;
        #pragma unroll 5
        for (int i = 0; i < H_/4; i += 2) {
            float4 e = e4[i],   h = h4[i];
            s0 += e.x*h.x + e.y*h.y + e.z*h.z + e.w*h.w;
            float4 e2 = e4[i+1], h2 = h4[i+1];
            s1 += e2.x*h2.x + e2.y*h2.y + e2.z*h2.z + e2.w*h2.w;
        }
        sc = (tid < lens[b]) ? (s0 + s1) : -1e9f;
    }
    // block max over 512 (inactive hold -1e30)
    {
        float m = sc;
        #pragma unroll
        for (int o = 16; o > 0; o >>= 1) m = fmaxf(m, __shfl_xor_sync(0xffffffffu, m, o));
        if (lane == 0) red[wrp] = m;
        __syncthreads();
        float mx = red[0];
        #pragma unroll
        for (int i = 1; i < 16; i++) mx = fmaxf(mx, red[i]);
        __syncthreads();
        float e = (tid < T_) ? expf(sc - mx) : 0.f;
        float s = e;
        #pragma unroll
        for (int o = 16; o > 0; o >>= 1) s += __shfl_xor_sync(0xffffffffu, s, o);
        if (lane == 0) red[wrp] = s;
        __syncthreads();
        float sum = 0.f;
        #pragma unroll
        for (int i = 0; i < 16; i++) sum += red[i];
        if (tid < T_) {
            float pp = e / sum;
            psh[tid] = pp;
            d_prob[n*T_ + tid] = pp;
        }
        __syncthreads();
    }

    // phase 3: context (threads 0..399, thread = h column)
    float ctxv = 0.f;
    if (tid < H_) {
        const float* ep = enc + (size_t)b*T_*H_ + tid;
        float c0=0.f, c1=0.f, c2=0.f, c3=0.f;
        for (int t = 0; t < T_; t += 4) {
            c0 += psh[t+0] * ep[(size_t)(t+0)*H_];
            c1 += psh[t+1] * ep[(size_t)(t+1)*H_];
            c2 += psh[t+2] * ep[(size_t)(t+2)*H_];
            c3 += psh[t+3] * ep[(size_t)(t+3)*H_];
        }
        ctxv = (c0 + c1) + (c2 + c3);
    }

    // phase 4: pointer-gen switch
    {
        float p = 0.f;
        if (tid < H_) {
            float x = d_dec[(size_t)(wi*N_ + n)*H_ + tid];
            p = hv*w_ratio[tid] + ctxv*w_ratio[H_+tid] + x*w_ratio[2*H_+tid];
        }
        #pragma unroll
        for (int o = 16; o > 0; o >>= 1) p += __shfl_xor_sync(0xffffffffu, p, o);
        if (lane == 0) red[wrp] = p;
        __syncthreads();
        if (tid == 0) {
            float s = 0.f;
            #pragma unroll
            for (int i = 0; i < 16; i++) s += red[i];
            d_sw[n] = 1.f / (1.f + expf(-(s + b_ratio[0])));
        }
        __syncthreads();
    }

    // phase 5: gates (step 0 only)
    if (wi == 0) {
        for (int g = 0; g < G_; g++) {
            float q = (tid < H_) ? ctxv * w_gate[g*H_ + tid] : 0.f;
            #pragma unroll
            for (int o = 16; o > 0; o >>= 1) q += __shfl_xor_sync(0xffffffffu, q, o);
            if (lane == 0) red[wrp] = q;
            __syncthreads();
            if (tid == 0) {
                float s = 0.f;
                #pragma unroll
                for (int i = 0; i < 16; i++) s += red[i];
                out[(size_t)N_*L_*V_ + (size_t)n*G_ + g] = s + b_gate[g];
            }
            __syncthreads();
        }
    }
}

// ---------------- finalize vocab part ----------------
__global__ void k_finalize(int wi, float* __restrict__ out)
{
    int n = blockIdx.y;
    int v = blockIdx.x * 256 + threadIdx.x;
    if (v >= V_) return;
    float scale = d_sw[n] / d_rowsum[n];
    out[((size_t)n*L_ + wi)*V_ + v] = scale * d_logits[(size_t)n*V_ + v];
}

// ---------------- pointer scatter ----------------
__global__ void k_scatter(int wi, const int* __restrict__ story, float* __restrict__ out)
{
    int n = blockIdx.x, t = threadIdx.x;
    int b0 = n % B_;
    float pv = d_prob[n*T_ + t] * (1.f - d_sw[n]);
    int v = story[b0*T_ + t];
    atomicAdd(&out[((size_t)n*L_ + wi)*V_ + v], pv);
}

// ---------------- host launcher ----------------
extern "C" void kernel_launch(void* const* d_in, const int* in_sizes, int n_in,
                              void* d_out, int out_size)
{
    const float* enc_hidden = (const float*)d_in[0];
    const float* enc_out    = (const float*)d_in[1];
    const float* emb        = (const float*)d_in[2];
    const float* w_ih       = (const float*)d_in[3];
    const float* w_hh       = (const float*)d_in[4];
    const float* b_ih       = (const float*)d_in[5];
    const float* b_hh       = (const float*)d_in[6];
    const float* w_ratio    = (const float*)d_in[7];
    const float* b_ratio    = (const float*)d_in[8];
    const float* w_gate     = (const float*)d_in[9];
    const float* b_gate     = (const float*)d_in[10];
    const float* slot_emb   = (const float*)d_in[11];
    const int*   lens       = (const int*)d_in[12];
    const int*   story      = (const int*)d_in[13];
    const int*   targets    = (const int*)d_in[14];
    const int*   domain_idx = (const int*)d_in[15];
    const int*   slotname_idx = (const int*)d_in[16];
    float* out = (float*)d_out;

    float *p_dec, *p_gi, *p_gh, *p_h, *p_logits;
    cudaGetSymbolAddress((void**)&p_dec, d_dec);
    cudaGetSymbolAddress((void**)&p_gi, d_gi);
    cudaGetSymbolAddress((void**)&p_gh, d_gh);
    cudaGetSymbolAddress((void**)&p_h, d_h);
    cudaGetSymbolAddress((void**)&p_logits, d_logits);

    // once per launch: padded bf16 embedding
    k_cvt_emb<<<(int)(((size_t)V_*KP + 255)/256), 256>>>(emb);

    // decoder inputs for all steps + h0
    k_prep<<<dim3(N_, L_), H_>>>(enc_hidden, emb, slot_emb, domain_idx, slotname_idx, targets);

    // input-side GRU gates for ALL steps in one GEMM
    k_gemm_abt<<<dim3((H3_ + 127)/128, (L_*N_ + 127)/128), 256>>>(
        p_dec, w_ih, p_gi, L_*N_, H3_, b_ih);

    for (int wi = 0; wi < L_; wi++) {
        int pin = wi & 1, pout = (wi + 1) & 1;
        float* hprev = p_h + (size_t)pin * N_ * H_;

        // hidden-side gates: 64x64 tiles -> 152 CTAs (was 40)
        k_gemm64<<<dim3((H3_ + 63)/64, (N_ + 63)/64), 128>>>(
            hprev, w_hh, p_gh, N_, H3_, b_hh);

        // fused GRU + attention + softmax + context + switch (+ gates)
        k_step<<<N_, 512>>>(wi, pin, pout, enc_out, lens,
                            w_ratio, b_ratio, w_gate, b_gate, out);

        // vocab GEMM on tensor cores via mma.sync (exp + rowsum fused)
        k_vocab_mma<<<dim3((V_ + 127)/128, 4), 256>>>(p_logits);

        k_finalize<<<dim3((V_ + 255)/256, N_), 256>>>(wi, out);
        k_scatter<<<N_, T_>>>(wi, story, out);
    }
}

// round 9
// speedup vs baseline: 1.5885x; 1.5885x over previous
#include <cuda_runtime.h>
#include <cuda_bf16.h>
#include <math.h>
#include <stdint.h>

#define B_   16
#define T_   256
#define V_   18000
#define NS_  30
#define L_   10
#define G_   3
#define H_   400
#define N_   480      // NS_*B_
#define H3_  1200
#define KDIM 400
#define KP   448      // K padded to 7*64 for bf16 MMA
#define NKC  7        // K chunks of 64
#define KSPL 5        // split-K factor for gh GEMM (5 x 80)
#define KSEG 80

// ---------------- scratch (static __device__, allowed) ----------------
__device__ float d_dec[L_*N_*H_];
__device__ float d_gi[L_*N_*H3_];
__device__ float d_ghp[KSPL][N_*H3_];    // split-K partials (11.5 MB)
__device__ float d_h[2][N_*H_];
__device__ float d_prob[N_*T_];
__device__ float d_ctx[N_*H_];
__device__ float d_sw[N_];
__device__ float d_rowsum[N_];
__device__ float d_logits[(size_t)N_*V_];
__device__ __nv_bfloat16 d_emb_bf[(size_t)V_*KP];
__device__ __nv_bfloat16 d_h_bf[512*KP];

// ---------------- emb -> padded bf16 (once per launch) ----------------
__global__ void k_cvt_emb(const float* __restrict__ emb)
{
    size_t i = (size_t)blockIdx.x * 256 + threadIdx.x;
    if (i >= (size_t)V_ * KP) return;
    int c = (int)(i % KP);
    int n = (int)(i / KP);
    float v = (c < H_) ? emb[(size_t)n * H_ + c] : 0.f;
    d_emb_bf[i] = __float2bfloat16(v);
}

// ================= mma.sync helpers =================
__device__ __forceinline__ void ldmat4(uint32_t* r, uint32_t addr)
{
    asm volatile("ldmatrix.sync.aligned.m8n8.x4.shared.b16 {%0,%1,%2,%3}, [%4];"
                 : "=r"(r[0]), "=r"(r[1]), "=r"(r[2]), "=r"(r[3]) : "r"(addr));
}
__device__ __forceinline__ void mma_bf16(float* d, const uint32_t* a, uint32_t b0, uint32_t b1)
{
    asm volatile(
        "mma.sync.aligned.m16n8k16.row.col.f32.bf16.bf16.f32 "
        "{%0,%1,%2,%3}, {%4,%5,%6,%7}, {%8,%9}, {%0,%1,%2,%3};"
        : "+f"(d[0]), "+f"(d[1]), "+f"(d[2]), "+f"(d[3])
        : "r"(a[0]), "r"(a[1]), "r"(a[2]), "r"(a[3]), "r"(b0), "r"(b1));
}

// ---------------- vocab GEMM via mma.sync ----------
__global__ void __launch_bounds__(256) k_vocab_mma(float* __restrict__ logits)
{
    __shared__ alignas(128) uint8_t As[16384];
    __shared__ alignas(128) uint8_t Bs[16384];
    __shared__ float srow[128];

    const int tid  = threadIdx.x;
    const int lane = tid & 31;
    const int wid  = tid >> 5;
    const int wm   = (wid & 1) * 64;
    const int wn   = (wid >> 1) * 32;
    const int m0   = blockIdx.y * 128;
    const int n0   = blockIdx.x * 128;
    const uint32_t aBase = (uint32_t)__cvta_generic_to_shared(As);
    const uint32_t bBase = (uint32_t)__cvta_generic_to_shared(Bs);

    float acc[4][4][4];
    #pragma unroll
    for (int i = 0; i < 4; i++)
        #pragma unroll
        for (int j = 0; j < 4; j++)
            #pragma unroll
            for (int q = 0; q < 4; q++) acc[i][j][q] = 0.f;

    for (int kc = 0; kc < NKC; kc++) {
        __syncthreads();
        #pragma unroll
        for (int x = tid; x < 1024; x += 256) {
            int r = x >> 3, c = x & 7;
            uint4 v = *(const uint4*)((const char*)d_h_bf + ((size_t)(m0 + r) * KP + kc * 64) * 2 + c * 16);
            uint32_t off = (uint32_t)(r * 128 + c * 16);
            *(uint4*)(As + (off ^ ((off >> 3) & 0x70))) = v;
        }
        #pragma unroll
        for (int x = tid; x < 1024; x += 256) {
            int r = x >> 3, c = x & 7;
            int gn = n0 + r;
            uint4 v = make_uint4(0u, 0u, 0u, 0u);
            if (gn < V_)
                v = *(const uint4*)((const char*)d_emb_bf + ((size_t)gn * KP + kc * 64) * 2 + c * 16);
            uint32_t off = (uint32_t)(r * 128 + c * 16);
            *(uint4*)(Bs + (off ^ ((off >> 3) & 0x70))) = v;
        }
        __syncthreads();

        #pragma unroll
        for (int ks = 0; ks < 4; ks++) {
            uint32_t af[4][4];
            #pragma unroll
            for (int mt = 0; mt < 4; mt++) {
                int row  = wm + mt * 16 + (lane & 7) + ((lane & 8) ? 8 : 0);
                int koff = ks * 32 + ((lane & 16) ? 16 : 0);
                uint32_t off = (uint32_t)(row * 128 + koff);
                ldmat4(af[mt], aBase + (off ^ ((off >> 3) & 0x70)));
            }
            uint32_t bfr[2][4];
            #pragma unroll
            for (int hh = 0; hh < 2; hh++) {
                int row  = wn + hh * 16 + (lane & 7) + ((lane & 16) ? 8 : 0);
                int koff = ks * 32 + ((lane & 8) ? 16 : 0);
                uint32_t off = (uint32_t)(row * 128 + koff);
                ldmat4(bfr[hh], bBase + (off ^ ((off >> 3) & 0x70)));
            }
            #pragma unroll
            for (int mt = 0; mt < 4; mt++)
                #pragma unroll
                for (int nt = 0; nt < 4; nt++)
                    mma_bf16(acc[mt][nt], af[mt],
                             bfr[nt >> 1][(nt & 1) * 2 + 0],
                             bfr[nt >> 1][(nt & 1) * 2 + 1]);
        }
    }

    if (tid < 128) srow[tid] = 0.f;
    __syncthreads();
    #pragma unroll
    for (int mt = 0; mt < 4; mt++) {
        int rlo = wm + mt * 16 + (lane >> 2);
        int rhi = rlo + 8;
        int gmlo = m0 + rlo, gmhi = m0 + rhi;
        float slo = 0.f, shi = 0.f;
        #pragma unroll
        for (int nt = 0; nt < 4; nt++) {
            int gcol = n0 + wn + nt * 8 + 2 * (lane & 3);
            if (gcol < V_) {
                if (gmlo < N_) {
                    float e0 = __expf(acc[mt][nt][0]);
                    float e1 = __expf(acc[mt][nt][1]);
                    *(float2*)&logits[(size_t)gmlo * V_ + gcol] = make_float2(e0, e1);
                    slo += e0 + e1;
                }
                if (gmhi < N_) {
                    float e2 = __expf(acc[mt][nt][2]);
                    float e3 = __expf(acc[mt][nt][3]);
                    *(float2*)&logits[(size_t)gmhi * V_ + gcol] = make_float2(e2, e3);
                    shi += e2 + e3;
                }
            }
        }
        slo += __shfl_xor_sync(0xffffffffu, slo, 1);
        slo += __shfl_xor_sync(0xffffffffu, slo, 2);
        shi += __shfl_xor_sync(0xffffffffu, shi, 1);
        shi += __shfl_xor_sync(0xffffffffu, shi, 2);
        if ((lane & 3) == 0) {
            if (gmlo < N_) atomicAdd(&srow[rlo], slo);
            if (gmhi < N_) atomicAdd(&srow[rhi], shi);
        }
    }
    __syncthreads();
    if (tid < 128 && m0 + tid < N_) atomicAdd(&d_rowsum[m0 + tid], srow[tid]);
}

// ---------------- K0: build decoder inputs + h0 ----------------
__global__ void k_prep(const float* __restrict__ enc_hidden,
                       const float* __restrict__ emb,
                       const float* __restrict__ slot_emb,
                       const int*   __restrict__ domain_idx,
                       const int*   __restrict__ slotname_idx,
                       const int*   __restrict__ targets)
{
    int n  = blockIdx.x;
    int wi = blockIdx.y;
    int h  = threadIdx.x;
    int slot = n / B_, b = n % B_;
    float v;
    if (wi == 0) {
        v = slot_emb[domain_idx[slot]*H_ + h] + slot_emb[slotname_idx[slot]*H_ + h];
        d_h[0][n*H_ + h] = enc_hidden[b*H_ + h];
    } else {
        int tok = targets[(b*NS_ + slot)*L_ + (wi-1)];
        v = emb[(size_t)tok*H_ + h];
    }
    d_dec[(size_t)(wi*N_ + n)*H_ + h] = v;
}

// ---------------- fp32 SIMT GEMM 128x128 (big gi GEMM, once) ----------------
__global__ void k_gemm_abt(const float* __restrict__ A, const float* __restrict__ Bm,
                           float* __restrict__ C, int M, int N,
                           const float* __restrict__ bias)
{
    __shared__ alignas(16) float As[8][128];
    __shared__ alignas(16) float Bs[8][128];
    const int tid = threadIdx.x;
    const int m0 = blockIdx.y * 128;
    const int n0 = blockIdx.x * 128;
    const int tm = (tid & 15) * 8;
    const int tn = (tid >> 4) * 8;

    float acc[8][8];
    #pragma unroll
    for (int i = 0; i < 8; i++)
        #pragma unroll
        for (int j = 0; j < 8; j++) acc[i][j] = 0.f;

    const int lr = tid >> 1;
    const int lk = (tid & 1) * 4;

    for (int k0 = 0; k0 < KDIM; k0 += 8) {
        float4 av = make_float4(0.f,0.f,0.f,0.f);
        float4 bv = make_float4(0.f,0.f,0.f,0.f);
        if (m0 + lr < M) av = *reinterpret_cast<const float4*>(A + (size_t)(m0+lr)*KDIM + k0 + lk);
        if (n0 + lr < N) bv = *reinterpret_cast<const float4*>(Bm + (size_t)(n0+lr)*KDIM + k0 + lk);
        __syncthreads();
        As[lk+0][lr]=av.x; As[lk+1][lr]=av.y; As[lk+2][lr]=av.z; As[lk+3][lr]=av.w;
        Bs[lk+0][lr]=bv.x; Bs[lk+1][lr]=bv.y; Bs[lk+2][lr]=bv.z; Bs[lk+3][lr]=bv.w;
        __syncthreads();
        #pragma unroll
        for (int kk = 0; kk < 8; kk++) {
            float4 a0 = *reinterpret_cast<float4*>(&As[kk][tm]);
            float4 a1 = *reinterpret_cast<float4*>(&As[kk][tm+4]);
            float4 b0 = *reinterpret_cast<float4*>(&Bs[kk][tn]);
            float4 b1 = *reinterpret_cast<float4*>(&Bs[kk][tn+4]);
            float a[8] = {a0.x,a0.y,a0.z,a0.w,a1.x,a1.y,a1.z,a1.w};
            float b[8] = {b0.x,b0.y,b0.z,b0.w,b1.x,b1.y,b1.z,b1.w};
            #pragma unroll
            for (int i = 0; i < 8; i++)
                #pragma unroll
                for (int j = 0; j < 8; j++)
                    acc[i][j] += a[i] * b[j];
        }
    }
    #pragma unroll
    for (int i = 0; i < 8; i++) {
        int m = m0 + tm + i;
        if (m < M) {
            #pragma unroll
            for (int j = 0; j < 8; j++) {
                int n = n0 + tn + j;
                if (n < N) {
                    float v = acc[i][j];
                    if (bias) v += bias[n];
                    C[(size_t)m*N + n] = v;
                }
            }
        }
    }
}

// ---------------- split-K gh GEMM: partial[s] = hprev @ W_hh[:,ks]^T -----------
// 64x64 tile, 256 threads, BK=16, K segment = 80. grid (19, 8, KSPL) = 760 CTAs.
__global__ void __launch_bounds__(256) k_gemm_gh(const float* __restrict__ A,
                                                 const float* __restrict__ Bm)
{
    __shared__ alignas(16) float As[16][64];
    __shared__ alignas(16) float Bs[16][64];
    const int tid = threadIdx.x;
    const int m0 = blockIdx.y * 64;
    const int n0 = blockIdx.x * 64;
    const int s  = blockIdx.z;
    const int kbeg = s * KSEG;
    float* Cp = d_ghp[s];

    const int tm = (tid & 15) * 4;
    const int tn = (tid >> 4) * 4;

    float acc[4][4];
    #pragma unroll
    for (int i = 0; i < 4; i++)
        #pragma unroll
        for (int j = 0; j < 4; j++) acc[i][j] = 0.f;

    const int lr = tid >> 2;         // 0..63
    const int lk = (tid & 3) * 4;    // 0,4,8,12

    for (int k0 = kbeg; k0 < kbeg + KSEG; k0 += 16) {
        __syncthreads();
        {
            float4 v = make_float4(0.f,0.f,0.f,0.f);
            if (m0 + lr < N_) v = *(const float4*)(A + (size_t)(m0+lr)*KDIM + k0 + lk);
            As[lk+0][lr]=v.x; As[lk+1][lr]=v.y; As[lk+2][lr]=v.z; As[lk+3][lr]=v.w;
        }
        {
            float4 v = make_float4(0.f,0.f,0.f,0.f);
            if (n0 + lr < H3_) v = *(const float4*)(Bm + (size_t)(n0+lr)*KDIM + k0 + lk);
            Bs[lk+0][lr]=v.x; Bs[lk+1][lr]=v.y; Bs[lk+2][lr]=v.z; Bs[lk+3][lr]=v.w;
        }
        __syncthreads();
        #pragma unroll
        for (int kk = 0; kk < 16; kk++) {
            float4 a4 = *(float4*)&As[kk][tm];
            float4 b4 = *(float4*)&Bs[kk][tn];
            float a[4] = {a4.x, a4.y, a4.z, a4.w};
            float b[4] = {b4.x, b4.y, b4.z, b4.w};
            #pragma unroll
            for (int i = 0; i < 4; i++)
                #pragma unroll
                for (int j = 0; j < 4; j++)
                    acc[i][j] += a[i] * b[j];
        }
    }
    #pragma unroll
    for (int i = 0; i < 4; i++) {
        int m = m0 + tm + i;
        if (m < N_) {
            #pragma unroll
            for (int j = 0; j < 4; j++) {
                int n = n0 + tn + j;
                if (n < H3_) Cp[(size_t)m*H3_ + n] = acc[i][j];
            }
        }
    }
}

// ---------------- GRU gate fusion (sums split-K partials + b_hh) ----------------
__global__ void k_gru(int wi, int pin, int pout, const float* __restrict__ b_hh)
{
    int n = blockIdx.x;
    int h = threadIdx.x;
    const float* gi = &d_gi[(size_t)(wi*N_ + n)*H3_];
    size_t base = (size_t)n*H3_;
    float g0 = b_hh[h], g1 = b_hh[H_+h], g2 = b_hh[2*H_+h];
    #pragma unroll
    for (int s = 0; s < KSPL; s++) {
        g0 += d_ghp[s][base + h];
        g1 += d_ghp[s][base + H_ + h];
        g2 += d_ghp[s][base + 2*H_ + h];
    }
    float hp = d_h[pin][n*H_ + h];
    float r  = 1.f / (1.f + expf(-(gi[h]      + g0)));
    float z  = 1.f / (1.f + expf(-(gi[H_+h]   + g1)));
    float nn = tanhf(gi[2*H_+h] + r * g2);
    float hv = (1.f - z) * nn + z * hp;
    d_h[pout][n*H_ + h] = hv;
    d_h_bf[n*KP + h] = __float2bfloat16(hv);
    if (h == 0) d_rowsum[n] = 0.f;
}

// ---------------- attention scores ----------------
__global__ void k_scores(const float* __restrict__ enc, const int* __restrict__ lens, int pcur)
{
    __shared__ alignas(16) float hsh[H_];
    int n = blockIdx.x;
    int t = threadIdx.x;
    int b = n % B_;
    for (int i = t; i < H_; i += 256) hsh[i] = d_h[pcur][n*H_ + i];
    __syncthreads();
    const float4* e4 = reinterpret_cast<const float4*>(enc + ((size_t)b*T_ + t)*H_);
    const float4* h4 = reinterpret_cast<const float4*>(hsh);
    float s = 0.f;
    #pragma unroll 4
    for (int i = 0; i < H_/4; i++) {
        float4 e = e4[i], hh = h4[i];
        s += e.x*hh.x + e.y*hh.y + e.z*hh.z + e.w*hh.w;
    }
    d_prob[n*T_ + t] = (t < lens[b]) ? s : -1e9f;
}

// ---------------- softmax over T ----------------
__global__ void k_softmax_t()
{
    int n = blockIdx.x, t = threadIdx.x;
    __shared__ float red[8];
    int w = t >> 5, ln = t & 31;
    float v = d_prob[n*T_ + t];
    float m = v;
    #pragma unroll
    for (int o = 16; o > 0; o >>= 1) m = fmaxf(m, __shfl_xor_sync(0xffffffffu, m, o));
    if (ln == 0) red[w] = m;
    __syncthreads();
    float mx = red[0];
    #pragma unroll
    for (int i = 1; i < 8; i++) mx = fmaxf(mx, red[i]);
    __syncthreads();
    float e = expf(v - mx);
    float s = e;
    #pragma unroll
    for (int o = 16; o > 0; o >>= 1) s += __shfl_xor_sync(0xffffffffu, s, o);
    if (ln == 0) red[w] = s;
    __syncthreads();
    float sum = 0.f;
    #pragma unroll
    for (int i = 0; i < 8; i++) sum += red[i];
    d_prob[n*T_ + t] = e / sum;
}

// ---------------- context ----------------
__global__ void k_ctx(const float* __restrict__ enc)
{
    __shared__ float psh[T_];
    int n = blockIdx.x;
    int h = threadIdx.x;
    int b = n % B_;
    if (h < T_) psh[h] = d_prob[n*T_ + h];
    __syncthreads();
    float acc = 0.f;
    #pragma unroll 4
    for (int t = 0; t < T_; t++)
        acc += psh[t] * enc[((size_t)b*T_ + t)*H_ + h];
    d_ctx[n*H_ + h] = acc;
}

// ---------------- switch (+ gates at step 0) ----------------
__device__ __forceinline__ float reduce128(float v, float* sm)
{
    #pragma unroll
    for (int o = 16; o > 0; o >>= 1) v += __shfl_xor_sync(0xffffffffu, v, o);
    int w = threadIdx.x >> 5, ln = threadIdx.x & 31;
    if (ln == 0) sm[w] = v;
    __syncthreads();
    float r = sm[0] + sm[1] + sm[2] + sm[3];
    __syncthreads();
    return r;
}

__global__ void k_switch(int wi, int pcur,
                         const float* __restrict__ w_ratio, const float* __restrict__ b_ratio,
                         const float* __restrict__ w_gate,  const float* __restrict__ b_gate,
                         float* __restrict__ out)
{
    __shared__ float sm[4];
    int n = blockIdx.x, tid = threadIdx.x;
    const float* hn = &d_h[pcur][n*H_];
    const float* cx = &d_ctx[n*H_];
    const float* xx = &d_dec[(size_t)(wi*N_ + n)*H_];
    float p = 0.f;
    for (int j = tid; j < H_; j += 128)
        p += hn[j]*w_ratio[j] + cx[j]*w_ratio[H_+j] + xx[j]*w_ratio[2*H_+j];
    p = reduce128(p, sm);
    if (tid == 0) d_sw[n] = 1.f / (1.f + expf(-(p + b_ratio[0])));
    if (wi == 0) {
        for (int g = 0; g < G_; g++) {
            float q = 0.f;
            for (int j = tid; j < H_; j += 128) q += cx[j] * w_gate[g*H_ + j];
            q = reduce128(q, sm);
            if (tid == 0)
                out[(size_t)N_*L_*V_ + (size_t)n*G_ + g] = q + b_gate[g];
        }
    }
}

// ---------------- finalize vocab part ----------------
__global__ void k_finalize(int wi, float* __restrict__ out)
{
    int n = blockIdx.y;
    int v = blockIdx.x * 256 + threadIdx.x;
    if (v >= V_) return;
    float scale = d_sw[n] / d_rowsum[n];
    out[((size_t)n*L_ + wi)*V_ + v] = scale * d_logits[(size_t)n*V_ + v];
}

// ---------------- pointer scatter ----------------
__global__ void k_scatter(int wi, const int* __restrict__ story, float* __restrict__ out)
{
    int n = blockIdx.x, t = threadIdx.x;
    int b0 = n % B_;
    float pv = d_prob[n*T_ + t] * (1.f - d_sw[n]);
    int v = story[b0*T_ + t];
    atomicAdd(&out[((size_t)n*L_ + wi)*V_ + v], pv);
}

// ---------------- host launcher ----------------
extern "C" void kernel_launch(void* const* d_in, const int* in_sizes, int n_in,
                              void* d_out, int out_size)
{
    const float* enc_hidden = (const float*)d_in[0];
    const float* enc_out    = (const float*)d_in[1];
    const float* emb        = (const float*)d_in[2];
    const float* w_ih       = (const float*)d_in[3];
    const float* w_hh       = (const float*)d_in[4];
    const float* b_ih       = (const float*)d_in[5];
    const float* b_hh       = (const float*)d_in[6];
    const float* w_ratio    = (const float*)d_in[7];
    const float* b_ratio    = (const float*)d_in[8];
    const float* w_gate     = (const float*)d_in[9];
    const float* b_gate     = (const float*)d_in[10];
    const float* slot_emb   = (const float*)d_in[11];
    const int*   lens       = (const int*)d_in[12];
    const int*   story      = (const int*)d_in[13];
    const int*   targets    = (const int*)d_in[14];
    const int*   domain_idx = (const int*)d_in[15];
    const int*   slotname_idx = (const int*)d_in[16];
    float* out = (float*)d_out;

    float *p_dec, *p_gi, *p_h, *p_logits;
    cudaGetSymbolAddress((void**)&p_dec, d_dec);
    cudaGetSymbolAddress((void**)&p_gi, d_gi);
    cudaGetSymbolAddress((void**)&p_h, d_h);
    cudaGetSymbolAddress((void**)&p_logits, d_logits);

    // once per launch: padded bf16 embedding
    k_cvt_emb<<<(int)(((size_t)V_*KP + 255)/256), 256>>>(emb);

    // decoder inputs for all steps + h0
    k_prep<<<dim3(N_, L_), H_>>>(enc_hidden, emb, slot_emb, domain_idx, slotname_idx, targets);

    // input-side GRU gates for ALL steps in one GEMM
    k_gemm_abt<<<dim3((H3_ + 127)/128, (L_*N_ + 127)/128), 256>>>(
        p_dec, w_ih, p_gi, L_*N_, H3_, b_ih);

    for (int wi = 0; wi < L_; wi++) {
        int pin = wi & 1, pout = (wi + 1) & 1;
        float* hprev = p_h + (size_t)pin * N_ * H_;

        // hidden-side gates: split-K partials, 760 CTAs
        k_gemm_gh<<<dim3((H3_ + 63)/64, (N_ + 63)/64, KSPL), 256>>>(hprev, w_hh);

        // GRU combine (sums partials + b_hh) -> h_new ; zeros rowsum
        k_gru<<<N_, H_>>>(wi, pin, pout, b_hh);

        k_scores<<<N_, T_>>>(enc_out, lens, pout);
        k_softmax_t<<<N_, T_>>>();
        k_ctx<<<N_, H_>>>(enc_out);

        k_switch<<<N_, 128>>>(wi, pout, w_ratio, b_ratio, w_gate, b_gate, out);

        // vocab GEMM on tensor cores via mma.sync (exp + rowsum fused)
        k_vocab_mma<<<dim3((V_ + 127)/128, 4), 256>>>(p_logits);

        k_finalize<<<dim3((V_ + 255)/256, N_), 256>>>(wi, out);
        k_scatter<<<N_, T_>>>(wi, story, out);
    }
}

// round 10
// speedup vs baseline: 2.0358x; 1.2815x over previous
#include <cuda_runtime.h>
#include <cuda_bf16.h>
#include <math.h>
#include <stdint.h>

#define B_   16
#define T_   256
#define V_   18000
#define NS_  30
#define L_   10
#define G_   3
#define H_   400
#define N_   480      // NS_*B_
#define H3_  1200
#define KDIM 400
#define KP   448      // K padded to 7*64 for bf16 MMA
#define NKC  7        // K chunks of 64
#define KSPL 5        // split-K factor for gh GEMM
#define KSEG 80

// ---------------- scratch ----------------
__device__ float d_dec[L_*N_*H_];
__device__ float d_gi[L_*N_*H3_];
__device__ float d_ghp[KSPL][N_*H3_];
__device__ float d_h[2][N_*H_];
__device__ float d_prob[N_*T_];
__device__ float d_ctxp[4][N_*H_];       // context partials (t-quarters)
__device__ float d_sw[N_];
__device__ float d_rowsum[N_];
__device__ float d_logits[(size_t)N_*V_];
__device__ __nv_bfloat16 d_emb_bf[(size_t)V_*KP];
__device__ __nv_bfloat16 d_h_bf[512*KP];

// ---------------- emb -> padded bf16 ----------------
__global__ void k_cvt_emb(const float* __restrict__ emb)
{
    size_t i = (size_t)blockIdx.x * 256 + threadIdx.x;
    if (i >= (size_t)V_ * KP) return;
    int c = (int)(i % KP);
    int n = (int)(i / KP);
    float v = (c < H_) ? emb[(size_t)n * H_ + c] : 0.f;
    d_emb_bf[i] = __float2bfloat16(v);
}

// ================= mma.sync + cp.async helpers =================
__device__ __forceinline__ void ldmat4(uint32_t* r, uint32_t addr)
{
    asm volatile("ldmatrix.sync.aligned.m8n8.x4.shared.b16 {%0,%1,%2,%3}, [%4];"
                 : "=r"(r[0]), "=r"(r[1]), "=r"(r[2]), "=r"(r[3]) : "r"(addr));
}
__device__ __forceinline__ void mma_bf16(float* d, const uint32_t* a, uint32_t b0, uint32_t b1)
{
    asm volatile(
        "mma.sync.aligned.m16n8k16.row.col.f32.bf16.bf16.f32 "
        "{%0,%1,%2,%3}, {%4,%5,%6,%7}, {%8,%9}, {%0,%1,%2,%3};"
        : "+f"(d[0]), "+f"(d[1]), "+f"(d[2]), "+f"(d[3])
        : "r"(a[0]), "r"(a[1]), "r"(a[2]), "r"(a[3]), "r"(b0), "r"(b1));
}
__device__ __forceinline__ void cpa16(uint32_t dst, const void* src)
{
    asm volatile("cp.async.ca.shared.global [%0], [%1], 16;" :: "r"(dst), "l"(src));
}
__device__ __forceinline__ void cpa16z(uint32_t dst, const void* src, int valid)
{
    asm volatile("cp.async.ca.shared.global [%0], [%1], 16, %2;"
                 :: "r"(dst), "l"(src), "r"(valid ? 16 : 0));
}
#define CP_COMMIT() asm volatile("cp.async.commit_group;" ::: "memory")
#define CP_WAIT0()  asm volatile("cp.async.wait_group 0;" ::: "memory")

// ---------------- vocab GEMM (mma.sync, cp.async pipelined) ----------
// dyn smem: [A0 16K][A1 16K][B0 16K][B1 16K][srow 512B]
#define VSM_BYTES (65536 + 512)
__global__ void __launch_bounds__(256) k_vocab_mma(float* __restrict__ logits)
{
    extern __shared__ uint8_t sm[];
    float* srow = (float*)(sm + 65536);
    const int tid  = threadIdx.x;
    const int lane = tid & 31;
    const int wid  = tid >> 5;
    const int wm   = (wid & 1) * 64;
    const int wn   = (wid >> 1) * 32;
    const int m0   = blockIdx.y * 128;
    const int n0   = blockIdx.x * 128;
    const uint32_t smBase = (uint32_t)__cvta_generic_to_shared(sm);

    float acc[4][4][4];
    #pragma unroll
    for (int i = 0; i < 4; i++)
        #pragma unroll
        for (int j = 0; j < 4; j++)
            #pragma unroll
            for (int q = 0; q < 4; q++) acc[i][j][q] = 0.f;

    const int lr = tid >> 3, lc = tid & 7;   // 32 rows per pass, 4 passes

    // prefetch issue for chunk kc into buffer bs
    auto issue = [&](int kc, int bs) {
        uint32_t aDst = smBase + bs * 16384;
        uint32_t bDst = smBase + 32768 + bs * 16384;
        #pragma unroll
        for (int p = 0; p < 4; p++) {
            int r = lr + p * 32;
            uint32_t off = (uint32_t)(r * 128 + lc * 16);
            uint32_t sw = off ^ ((off >> 3) & 0x70);
            cpa16(aDst + sw, (const char*)d_h_bf + ((size_t)(m0 + r) * KP + kc * 64) * 2 + lc * 16);
            int gn = n0 + r;
            cpa16z(bDst + sw, (const char*)d_emb_bf + ((size_t)(gn < V_ ? gn : 0) * KP + kc * 64) * 2 + lc * 16,
                   gn < V_);
        }
    };

    issue(0, 0); CP_COMMIT();
    for (int kc = 0; kc < NKC; kc++) {
        CP_WAIT0();
        __syncthreads();
        if (kc < NKC - 1) { issue(kc + 1, (kc + 1) & 1); CP_COMMIT(); }
        const uint32_t aBase = smBase + (kc & 1) * 16384;
        const uint32_t bBase = smBase + 32768 + (kc & 1) * 16384;
        #pragma unroll
        for (int ks = 0; ks < 4; ks++) {
            uint32_t af[4][4];
            #pragma unroll
            for (int mt = 0; mt < 4; mt++) {
                int row  = wm + mt * 16 + (lane & 7) + ((lane & 8) ? 8 : 0);
                int koff = ks * 32 + ((lane & 16) ? 16 : 0);
                uint32_t off = (uint32_t)(row * 128 + koff);
                ldmat4(af[mt], aBase + (off ^ ((off >> 3) & 0x70)));
            }
            uint32_t bfr[2][4];
            #pragma unroll
            for (int hh = 0; hh < 2; hh++) {
                int row  = wn + hh * 16 + (lane & 7) + ((lane & 16) ? 8 : 0);
                int koff = ks * 32 + ((lane & 8) ? 16 : 0);
                uint32_t off = (uint32_t)(row * 128 + koff);
                ldmat4(bfr[hh], bBase + (off ^ ((off >> 3) & 0x70)));
            }
            #pragma unroll
            for (int mt = 0; mt < 4; mt++)
                #pragma unroll
                for (int nt = 0; nt < 4; nt++)
                    mma_bf16(acc[mt][nt], af[mt],
                             bfr[nt >> 1][(nt & 1) * 2 + 0],
                             bfr[nt >> 1][(nt & 1) * 2 + 1]);
        }
    }

    if (tid < 128) srow[tid] = 0.f;
    __syncthreads();
    #pragma unroll
    for (int mt = 0; mt < 4; mt++) {
        int rlo = wm + mt * 16 + (lane >> 2);
        int rhi = rlo + 8;
        int gmlo = m0 + rlo, gmhi = m0 + rhi;
        float slo = 0.f, shi = 0.f;
        #pragma unroll
        for (int nt = 0; nt < 4; nt++) {
            int gcol = n0 + wn + nt * 8 + 2 * (lane & 3);
            if (gcol < V_) {
                if (gmlo < N_) {
                    float e0 = __expf(acc[mt][nt][0]);
                    float e1 = __expf(acc[mt][nt][1]);
                    *(float2*)&logits[(size_t)gmlo * V_ + gcol] = make_float2(e0, e1);
                    slo += e0 + e1;
                }
                if (gmhi < N_) {
                    float e2 = __expf(acc[mt][nt][2]);
                    float e3 = __expf(acc[mt][nt][3]);
                    *(float2*)&logits[(size_t)gmhi * V_ + gcol] = make_float2(e2, e3);
                    shi += e2 + e3;
                }
            }
        }
        slo += __shfl_xor_sync(0xffffffffu, slo, 1);
        slo += __shfl_xor_sync(0xffffffffu, slo, 2);
        shi += __shfl_xor_sync(0xffffffffu, shi, 1);
        shi += __shfl_xor_sync(0xffffffffu, shi, 2);
        if ((lane & 3) == 0) {
            if (gmlo < N_) atomicAdd(&srow[rlo], slo);
            if (gmhi < N_) atomicAdd(&srow[rhi], shi);
        }
    }
    __syncthreads();
    if (tid < 128 && m0 + tid < N_) atomicAdd(&d_rowsum[m0 + tid], srow[tid]);
}

// ---------------- K0: build decoder inputs + h0 ----------------
__global__ void k_prep(const float* __restrict__ enc_hidden,
                       const float* __restrict__ emb,
                       const float* __restrict__ slot_emb,
                       const int*   __restrict__ domain_idx,
                       const int*   __restrict__ slotname_idx,
                       const int*   __restrict__ targets)
{
    int n  = blockIdx.x;
    int wi = blockIdx.y;
    int h  = threadIdx.x;
    int slot = n / B_, b = n % B_;
    float v;
    if (wi == 0) {
        v = slot_emb[domain_idx[slot]*H_ + h] + slot_emb[slotname_idx[slot]*H_ + h];
        d_h[0][n*H_ + h] = enc_hidden[b*H_ + h];
    } else {
        int tok = targets[(b*NS_ + slot)*L_ + (wi-1)];
        v = emb[(size_t)tok*H_ + h];
    }
    d_dec[(size_t)(wi*N_ + n)*H_ + h] = v;
}

// ---------------- fp32 SIMT GEMM 128x128 (gi GEMM, once) ----------------
__global__ void k_gemm_abt(const float* __restrict__ A, const float* __restrict__ Bm,
                           float* __restrict__ C, int M, int N,
                           const float* __restrict__ bias)
{
    __shared__ alignas(16) float As[8][128];
    __shared__ alignas(16) float Bs[8][128];
    const int tid = threadIdx.x;
    const int m0 = blockIdx.y * 128;
    const int n0 = blockIdx.x * 128;
    const int tm = (tid & 15) * 8;
    const int tn = (tid >> 4) * 8;

    float acc[8][8];
    #pragma unroll
    for (int i = 0; i < 8; i++)
        #pragma unroll
        for (int j = 0; j < 8; j++) acc[i][j] = 0.f;

    const int lr = tid >> 1;
    const int lk = (tid & 1) * 4;

    for (int k0 = 0; k0 < KDIM; k0 += 8) {
        float4 av = make_float4(0.f,0.f,0.f,0.f);
        float4 bv = make_float4(0.f,0.f,0.f,0.f);
        if (m0 + lr < M) av = *reinterpret_cast<const float4*>(A + (size_t)(m0+lr)*KDIM + k0 + lk);
        if (n0 + lr < N) bv = *reinterpret_cast<const float4*>(Bm + (size_t)(n0+lr)*KDIM + k0 + lk);
        __syncthreads();
        As[lk+0][lr]=av.x; As[lk+1][lr]=av.y; As[lk+2][lr]=av.z; As[lk+3][lr]=av.w;
        Bs[lk+0][lr]=bv.x; Bs[lk+1][lr]=bv.y; Bs[lk+2][lr]=bv.z; Bs[lk+3][lr]=bv.w;
        __syncthreads();
        #pragma unroll
        for (int kk = 0; kk < 8; kk++) {
            float4 a0 = *reinterpret_cast<float4*>(&As[kk][tm]);
            float4 a1 = *reinterpret_cast<float4*>(&As[kk][tm+4]);
            float4 b0 = *reinterpret_cast<float4*>(&Bs[kk][tn]);
            float4 b1 = *reinterpret_cast<float4*>(&Bs[kk][tn+4]);
            float a[8] = {a0.x,a0.y,a0.z,a0.w,a1.x,a1.y,a1.z,a1.w};
            float b[8] = {b0.x,b0.y,b0.z,b0.w,b1.x,b1.y,b1.z,b1.w};
            #pragma unroll
            for (int i = 0; i < 8; i++)
                #pragma unroll
                for (int j = 0; j < 8; j++)
                    acc[i][j] += a[i] * b[j];
        }
    }
    #pragma unroll
    for (int i = 0; i < 8; i++) {
        int m = m0 + tm + i;
        if (m < M) {
            #pragma unroll
            for (int j = 0; j < 8; j++) {
                int n = n0 + tn + j;
                if (n < N) {
                    float v = acc[i][j];
                    if (bias) v += bias[n];
                    C[(size_t)m*N + n] = v;
                }
            }
        }
    }
}

// ---------------- split-K gh GEMM ----------------
__global__ void __launch_bounds__(256) k_gemm_gh(const float* __restrict__ A,
                                                 const float* __restrict__ Bm)
{
    __shared__ alignas(16) float As[16][64];
    __shared__ alignas(16) float Bs[16][64];
    const int tid = threadIdx.x;
    const int m0 = blockIdx.y * 64;
    const int n0 = blockIdx.x * 64;
    const int s  = blockIdx.z;
    const int kbeg = s * KSEG;
    float* Cp = d_ghp[s];

    const int tm = (tid & 15) * 4;
    const int tn = (tid >> 4) * 4;

    float acc[4][4];
    #pragma unroll
    for (int i = 0; i < 4; i++)
        #pragma unroll
        for (int j = 0; j < 4; j++) acc[i][j] = 0.f;

    const int lr = tid >> 2;
    const int lk = (tid & 3) * 4;

    for (int k0 = kbeg; k0 < kbeg + KSEG; k0 += 16) {
        __syncthreads();
        {
            float4 v = make_float4(0.f,0.f,0.f,0.f);
            if (m0 + lr < N_) v = *(const float4*)(A + (size_t)(m0+lr)*KDIM + k0 + lk);
            As[lk+0][lr]=v.x; As[lk+1][lr]=v.y; As[lk+2][lr]=v.z; As[lk+3][lr]=v.w;
        }
        {
            float4 v = make_float4(0.f,0.f,0.f,0.f);
            if (n0 + lr < H3_) v = *(const float4*)(Bm + (size_t)(n0+lr)*KDIM + k0 + lk);
            Bs[lk+0][lr]=v.x; Bs[lk+1][lr]=v.y; Bs[lk+2][lr]=v.z; Bs[lk+3][lr]=v.w;
        }
        __syncthreads();
        #pragma unroll
        for (int kk = 0; kk < 16; kk++) {
            float4 a4 = *(float4*)&As[kk][tm];
            float4 b4 = *(float4*)&Bs[kk][tn];
            float a[4] = {a4.x, a4.y, a4.z, a4.w};
            float b[4] = {b4.x, b4.y, b4.z, b4.w};
            #pragma unroll
            for (int i = 0; i < 4; i++)
                #pragma unroll
                for (int j = 0; j < 4; j++)
                    acc[i][j] += a[i] * b[j];
        }
    }
    #pragma unroll
    for (int i = 0; i < 4; i++) {
        int m = m0 + tm + i;
        if (m < N_) {
            #pragma unroll
            for (int j = 0; j < 4; j++) {
                int n = n0 + tn + j;
                if (n < H3_) Cp[(size_t)m*H3_ + n] = acc[i][j];
            }
        }
    }
}

// ---------------- GRU combine ----------------
__global__ void k_gru(int wi, int pin, int pout, const float* __restrict__ b_hh)
{
    int n = blockIdx.x;
    int h = threadIdx.x;
    const float* gi = &d_gi[(size_t)(wi*N_ + n)*H3_];
    size_t base = (size_t)n*H3_;
    float g0 = b_hh[h], g1 = b_hh[H_+h], g2 = b_hh[2*H_+h];
    #pragma unroll
    for (int s = 0; s < KSPL; s++) {
        g0 += d_ghp[s][base + h];
        g1 += d_ghp[s][base + H_ + h];
        g2 += d_ghp[s][base + 2*H_ + h];
    }
    float hp = d_h[pin][n*H_ + h];
    float r  = 1.f / (1.f + expf(-(gi[h]      + g0)));
    float z  = 1.f / (1.f + expf(-(gi[H_+h]   + g1)));
    float nn = tanhf(gi[2*H_+h] + r * g2);
    float hv = (1.f - z) * nn + z * hp;
    d_h[pout][n*H_ + h] = hv;
    d_h_bf[n*KP + h] = __float2bfloat16(hv);
    if (h == 0) d_rowsum[n] = 0.f;
}

// ---------------- slot-grouped attention scores ----------------
// block = (b, slot-group of 10); 256 threads (one per t). enc read once per group.
__global__ void __launch_bounds__(256) k_scores_g(const float* __restrict__ enc,
                                                  const int* __restrict__ lens, int pcur)
{
    __shared__ alignas(16) float hsh[10][H_];
    const int b  = blockIdx.x;
    const int s0 = blockIdx.y * 10;
    const int t  = threadIdx.x;

    for (int i = t; i < 10 * H_; i += 256) {
        int s = i / H_, j = i % H_;
        hsh[s][j] = d_h[pcur][((s0 + s) * B_ + b) * H_ + j];
    }
    __syncthreads();

    float acc[10];
    #pragma unroll
    for (int s = 0; s < 10; s++) acc[s] = 0.f;
    const float4* e4 = (const float4*)(enc + ((size_t)b * T_ + t) * H_);
    for (int i = 0; i < H_ / 4; i++) {
        float4 e = e4[i];
        #pragma unroll
        for (int s = 0; s < 10; s++) {
            float4 h = ((const float4*)hsh[s])[i];
            acc[s] += e.x*h.x + e.y*h.y + e.z*h.z + e.w*h.w;
        }
    }
    int len = lens[b];
    #pragma unroll
    for (int s = 0; s < 10; s++)
        d_prob[((s0 + s) * B_ + b) * T_ + t] = (t < len) ? acc[s] : -1e9f;
}

// ---------------- softmax over T ----------------
__global__ void k_softmax_t()
{
    int n = blockIdx.x, t = threadIdx.x;
    __shared__ float red[8];
    int w = t >> 5, ln = t & 31;
    float v = d_prob[n*T_ + t];
    float m = v;
    #pragma unroll
    for (int o = 16; o > 0; o >>= 1) m = fmaxf(m, __shfl_xor_sync(0xffffffffu, m, o));
    if (ln == 0) red[w] = m;
    __syncthreads();
    float mx = red[0];
    #pragma unroll
    for (int i = 1; i < 8; i++) mx = fmaxf(mx, red[i]);
    __syncthreads();
    float e = expf(v - mx);
    float s = e;
    #pragma unroll
    for (int o = 16; o > 0; o >>= 1) s += __shfl_xor_sync(0xffffffffu, s, o);
    if (ln == 0) red[w] = s;
    __syncthreads();
    float sum = 0.f;
    #pragma unroll
    for (int i = 0; i < 8; i++) sum += red[i];
    d_prob[n*T_ + t] = e / sum;
}

// ---------------- batch-grouped context (partials over t-quarters) ----------
// block = (b, quarter q); 400 threads (one per h); 30 slots in registers.
__global__ void __launch_bounds__(400) k_ctx_g(const float* __restrict__ enc)
{
    __shared__ float psh[30][64];
    const int b  = blockIdx.x;
    const int q  = blockIdx.y;
    const int t0 = q * 64;
    const int h  = threadIdx.x;

    for (int i = h; i < 30 * 64; i += 400) {
        int s = i >> 6, tt = i & 63;
        psh[s][tt] = d_prob[(s * B_ + b) * T_ + t0 + tt];
    }
    __syncthreads();

    float acc[30];
    #pragma unroll
    for (int s = 0; s < 30; s++) acc[s] = 0.f;
    #pragma unroll 2
    for (int tt = 0; tt < 64; tt++) {
        float e = enc[((size_t)b * T_ + t0 + tt) * H_ + h];
        #pragma unroll
        for (int s = 0; s < 30; s++) acc[s] += psh[s][tt] * e;
    }
    #pragma unroll
    for (int s = 0; s < 30; s++)
        d_ctxp[q][(s * B_ + b) * H_ + h] = acc[s];
}

// ---------------- switch (+ gates at step 0); sums ctx partials ----------------
__device__ __forceinline__ float reduce128(float v, float* sm)
{
    #pragma unroll
    for (int o = 16; o > 0; o >>= 1) v += __shfl_xor_sync(0xffffffffu, v, o);
    int w = threadIdx.x >> 5, ln = threadIdx.x & 31;
    if (ln == 0) sm[w] = v;
    __syncthreads();
    float r = sm[0] + sm[1] + sm[2] + sm[3];
    __syncthreads();
    return r;
}

__global__ void k_switch(int wi, int pcur,
                         const float* __restrict__ w_ratio, const float* __restrict__ b_ratio,
                         const float* __restrict__ w_gate,  const float* __restrict__ b_gate,
                         float* __restrict__ out)
{
    __shared__ float sm[4];
    int n = blockIdx.x, tid = threadIdx.x;
    const float* hn = &d_h[pcur][n*H_];
    const float* xx = &d_dec[(size_t)(wi*N_ + n)*H_];
    float p = 0.f;
    for (int j = tid; j < H_; j += 128) {
        float cx = d_ctxp[0][n*H_+j] + d_ctxp[1][n*H_+j] + d_ctxp[2][n*H_+j] + d_ctxp[3][n*H_+j];
        p += hn[j]*w_ratio[j] + cx*w_ratio[H_+j] + xx[j]*w_ratio[2*H_+j];
    }
    p = reduce128(p, sm);
    if (tid == 0) d_sw[n] = 1.f / (1.f + expf(-(p + b_ratio[0])));
    if (wi == 0) {
        for (int g = 0; g < G_; g++) {
            float q = 0.f;
            for (int j = tid; j < H_; j += 128) {
                float cx = d_ctxp[0][n*H_+j] + d_ctxp[1][n*H_+j] + d_ctxp[2][n*H_+j] + d_ctxp[3][n*H_+j];
                q += cx * w_gate[g*H_ + j];
            }
            q = reduce128(q, sm);
            if (tid == 0)
                out[(size_t)N_*L_*V_ + (size_t)n*G_ + g] = q + b_gate[g];
        }
    }
}

// ---------------- finalize vocab part ----------------
__global__ void k_finalize(int wi, float* __restrict__ out)
{
    int n = blockIdx.y;
    int v = blockIdx.x * 256 + threadIdx.x;
    if (v >= V_) return;
    float scale = d_sw[n] / d_rowsum[n];
    out[((size_t)n*L_ + wi)*V_ + v] = scale * d_logits[(size_t)n*V_ + v];
}

// ---------------- pointer scatter ----------------
__global__ void k_scatter(int wi, const int* __restrict__ story, float* __restrict__ out)
{
    int n = blockIdx.x, t = threadIdx.x;
    int b0 = n % B_;
    float pv = d_prob[n*T_ + t] * (1.f - d_sw[n]);
    int v = story[b0*T_ + t];
    atomicAdd(&out[((size_t)n*L_ + wi)*V_ + v], pv);
}

// ---------------- host launcher ----------------
extern "C" void kernel_launch(void* const* d_in, const int* in_sizes, int n_in,
                              void* d_out, int out_size)
{
    const float* enc_hidden = (const float*)d_in[0];
    const float* enc_out    = (const float*)d_in[1];
    const float* emb        = (const float*)d_in[2];
    const float* w_ih       = (const float*)d_in[3];
    const float* w_hh       = (const float*)d_in[4];
    const float* b_ih       = (const float*)d_in[5];
    const float* b_hh       = (const float*)d_in[6];
    const float* w_ratio    = (const float*)d_in[7];
    const float* b_ratio    = (const float*)d_in[8];
    const float* w_gate     = (const float*)d_in[9];
    const float* b_gate     = (const float*)d_in[10];
    const float* slot_emb   = (const float*)d_in[11];
    const int*   lens       = (const int*)d_in[12];
    const int*   story      = (const int*)d_in[13];
    const int*   targets    = (const int*)d_in[14];
    const int*   domain_idx = (const int*)d_in[15];
    const int*   slotname_idx = (const int*)d_in[16];
    float* out = (float*)d_out;

    float *p_dec, *p_gi, *p_h, *p_logits;
    cudaGetSymbolAddress((void**)&p_dec, d_dec);
    cudaGetSymbolAddress((void**)&p_gi, d_gi);
    cudaGetSymbolAddress((void**)&p_h, d_h);
    cudaGetSymbolAddress((void**)&p_logits, d_logits);

    cudaFuncSetAttribute(k_vocab_mma, cudaFuncAttributeMaxDynamicSharedMemorySize, VSM_BYTES);

    k_cvt_emb<<<(int)(((size_t)V_*KP + 255)/256), 256>>>(emb);

    k_prep<<<dim3(N_, L_), H_>>>(enc_hidden, emb, slot_emb, domain_idx, slotname_idx, targets);

    k_gemm_abt<<<dim3((H3_ + 127)/128, (L_*N_ + 127)/128), 256>>>(
        p_dec, w_ih, p_gi, L_*N_, H3_, b_ih);

    for (int wi = 0; wi < L_; wi++) {
        int pin = wi & 1, pout = (wi + 1) & 1;
        float* hprev = p_h + (size_t)pin * N_ * H_;

        k_gemm_gh<<<dim3((H3_ + 63)/64, (N_ + 63)/64, KSPL), 256>>>(hprev, w_hh);

        k_gru<<<N_, H_>>>(wi, pin, pout, b_hh);

        k_scores_g<<<dim3(B_, 3), 256>>>(enc_out, lens, pout);
        k_softmax_t<<<N_, T_>>>();
        k_ctx_g<<<dim3(B_, 4), 400>>>(enc_out);

        k_switch<<<N_, 128>>>(wi, pout, w_ratio, b_ratio, w_gate, b_gate, out);

        k_vocab_mma<<<dim3((V_ + 127)/128, 4), 256, VSM_BYTES>>>(p_logits);

        k_finalize<<<dim3((V_ + 255)/256, N_), 256>>>(wi, out);
        k_scatter<<<N_, T_>>>(wi, story, out);
    }
}

// round 11
// speedup vs baseline: 2.2018x; 1.0815x over previous
#include <cuda_runtime.h>
#include <cuda_bf16.h>
#include <math.h>
#include <stdint.h>

#define B_   16
#define T_   256
#define V_   18000
#define NS_  30
#define L_   10
#define G_   3
#define H_   400
#define N_   480      // NS_*B_
#define H3_  1200
#define KDIM 400
#define KP   448      // K padded to 7*64 for bf16 MMA
#define NKC  7        // K chunks of 64
#define KSPL 5        // split-K factor for gh GEMM
#define KSEG 80

// ---------------- scratch ----------------
__device__ float d_dec[L_*N_*H_];
__device__ float d_gi[L_*N_*H3_];
__device__ float d_ghp[KSPL][N_*H3_];
__device__ float d_h[2][N_*H_];
__device__ float d_prob[N_*T_];
__device__ float d_ctxp[4][N_*H_];
__device__ float d_sw[N_];
__device__ float d_rowsum[N_];
__device__ float d_logits[(size_t)N_*V_];
__device__ __nv_bfloat16 d_emb_bf[(size_t)V_*KP];
__device__ __nv_bfloat16 d_h_bf[512*KP];

// ---------------- emb -> padded bf16 ----------------
__global__ void k_cvt_emb(const float* __restrict__ emb)
{
    size_t i = (size_t)blockIdx.x * 256 + threadIdx.x;
    if (i >= (size_t)V_ * KP) return;
    int c = (int)(i % KP);
    int n = (int)(i / KP);
    float v = (c < H_) ? emb[(size_t)n * H_ + c] : 0.f;
    d_emb_bf[i] = __float2bfloat16(v);
}

// ================= mma.sync + cp.async helpers =================
__device__ __forceinline__ void ldmat4(uint32_t* r, uint32_t addr)
{
    asm volatile("ldmatrix.sync.aligned.m8n8.x4.shared.b16 {%0,%1,%2,%3}, [%4];"
                 : "=r"(r[0]), "=r"(r[1]), "=r"(r[2]), "=r"(r[3]) : "r"(addr));
}
__device__ __forceinline__ void mma_bf16(float* d, const uint32_t* a, uint32_t b0, uint32_t b1)
{
    asm volatile(
        "mma.sync.aligned.m16n8k16.row.col.f32.bf16.bf16.f32 "
        "{%0,%1,%2,%3}, {%4,%5,%6,%7}, {%8,%9}, {%0,%1,%2,%3};"
        : "+f"(d[0]), "+f"(d[1]), "+f"(d[2]), "+f"(d[3])
        : "r"(a[0]), "r"(a[1]), "r"(a[2]), "r"(a[3]), "r"(b0), "r"(b1));
}
__device__ __forceinline__ void cpa16(uint32_t dst, const void* src)
{
    asm volatile("cp.async.ca.shared.global [%0], [%1], 16;" :: "r"(dst), "l"(src));
}
__device__ __forceinline__ void cpa16z(uint32_t dst, const void* src, int valid)
{
    asm volatile("cp.async.ca.shared.global [%0], [%1], 16, %2;"
                 :: "r"(dst), "l"(src), "r"(valid ? 16 : 0));
}
#define CP_COMMIT() asm volatile("cp.async.commit_group;" ::: "memory")
#define CP_WAIT0()  asm volatile("cp.async.wait_group 0;" ::: "memory")

// ---------------- vocab GEMM (mma.sync, cp.async pipelined) ----------
#define VSM_BYTES (65536 + 512)
__global__ void __launch_bounds__(256) k_vocab_mma(float* __restrict__ logits)
{
    extern __shared__ uint8_t sm[];
    float* srow = (float*)(sm + 65536);
    const int tid  = threadIdx.x;
    const int lane = tid & 31;
    const int wid  = tid >> 5;
    const int wm   = (wid & 1) * 64;
    const int wn   = (wid >> 1) * 32;
    const int m0   = blockIdx.y * 128;
    const int n0   = blockIdx.x * 128;
    const uint32_t smBase = (uint32_t)__cvta_generic_to_shared(sm);

    float acc[4][4][4];
    #pragma unroll
    for (int i = 0; i < 4; i++)
        #pragma unroll
        for (int j = 0; j < 4; j++)
            #pragma unroll
            for (int q = 0; q < 4; q++) acc[i][j][q] = 0.f;

    const int lr = tid >> 3, lc = tid & 7;

    auto issue = [&](int kc, int bs) {
        uint32_t aDst = smBase + bs * 16384;
        uint32_t bDst = smBase + 32768 + bs * 16384;
        #pragma unroll
        for (int p = 0; p < 4; p++) {
            int r = lr + p * 32;
            uint32_t off = (uint32_t)(r * 128 + lc * 16);
            uint32_t sw = off ^ ((off >> 3) & 0x70);
            cpa16(aDst + sw, (const char*)d_h_bf + ((size_t)(m0 + r) * KP + kc * 64) * 2 + lc * 16);
            int gn = n0 + r;
            cpa16z(bDst + sw, (const char*)d_emb_bf + ((size_t)(gn < V_ ? gn : 0) * KP + kc * 64) * 2 + lc * 16,
                   gn < V_);
        }
    };

    issue(0, 0); CP_COMMIT();
    for (int kc = 0; kc < NKC; kc++) {
        CP_WAIT0();
        __syncthreads();
        if (kc < NKC - 1) { issue(kc + 1, (kc + 1) & 1); CP_COMMIT(); }
        const uint32_t aBase = smBase + (kc & 1) * 16384;
        const uint32_t bBase = smBase + 32768 + (kc & 1) * 16384;
        #pragma unroll
        for (int ks = 0; ks < 4; ks++) {
            uint32_t af[4][4];
            #pragma unroll
            for (int mt = 0; mt < 4; mt++) {
                int row  = wm + mt * 16 + (lane & 7) + ((lane & 8) ? 8 : 0);
                int koff = ks * 32 + ((lane & 16) ? 16 : 0);
                uint32_t off = (uint32_t)(row * 128 + koff);
                ldmat4(af[mt], aBase + (off ^ ((off >> 3) & 0x70)));
            }
            uint32_t bfr[2][4];
            #pragma unroll
            for (int hh = 0; hh < 2; hh++) {
                int row  = wn + hh * 16 + (lane & 7) + ((lane & 16) ? 8 : 0);
                int koff = ks * 32 + ((lane & 8) ? 16 : 0);
                uint32_t off = (uint32_t)(row * 128 + koff);
                ldmat4(bfr[hh], bBase + (off ^ ((off >> 3) & 0x70)));
            }
            #pragma unroll
            for (int mt = 0; mt < 4; mt++)
                #pragma unroll
                for (int nt = 0; nt < 4; nt++)
                    mma_bf16(acc[mt][nt], af[mt],
                             bfr[nt >> 1][(nt & 1) * 2 + 0],
                             bfr[nt >> 1][(nt & 1) * 2 + 1]);
        }
    }

    if (tid < 128) srow[tid] = 0.f;
    __syncthreads();
    #pragma unroll
    for (int mt = 0; mt < 4; mt++) {
        int rlo = wm + mt * 16 + (lane >> 2);
        int rhi = rlo + 8;
        int gmlo = m0 + rlo, gmhi = m0 + rhi;
        float slo = 0.f, shi = 0.f;
        #pragma unroll
        for (int nt = 0; nt < 4; nt++) {
            int gcol = n0 + wn + nt * 8 + 2 * (lane & 3);
            if (gcol < V_) {
                if (gmlo < N_) {
                    float e0 = __expf(acc[mt][nt][0]);
                    float e1 = __expf(acc[mt][nt][1]);
                    *(float2*)&logits[(size_t)gmlo * V_ + gcol] = make_float2(e0, e1);
                    slo += e0 + e1;
                }
                if (gmhi < N_) {
                    float e2 = __expf(acc[mt][nt][2]);
                    float e3 = __expf(acc[mt][nt][3]);
                    *(float2*)&logits[(size_t)gmhi * V_ + gcol] = make_float2(e2, e3);
                    shi += e2 + e3;
                }
            }
        }
        slo += __shfl_xor_sync(0xffffffffu, slo, 1);
        slo += __shfl_xor_sync(0xffffffffu, slo, 2);
        shi += __shfl_xor_sync(0xffffffffu, shi, 1);
        shi += __shfl_xor_sync(0xffffffffu, shi, 2);
        if ((lane & 3) == 0) {
            if (gmlo < N_) atomicAdd(&srow[rlo], slo);
            if (gmhi < N_) atomicAdd(&srow[rhi], shi);
        }
    }
    __syncthreads();
    if (tid < 128 && m0 + tid < N_) atomicAdd(&d_rowsum[m0 + tid], srow[tid]);
}

// ---------------- K0: build decoder inputs + h0 ----------------
__global__ void k_prep(const float* __restrict__ enc_hidden,
                       const float* __restrict__ emb,
                       const float* __restrict__ slot_emb,
                       const int*   __restrict__ domain_idx,
                       const int*   __restrict__ slotname_idx,
                       const int*   __restrict__ targets)
{
    int n  = blockIdx.x;
    int wi = blockIdx.y;
    int h  = threadIdx.x;
    int slot = n / B_, b = n % B_;
    float v;
    if (wi == 0) {
        v = slot_emb[domain_idx[slot]*H_ + h] + slot_emb[slotname_idx[slot]*H_ + h];
        d_h[0][n*H_ + h] = enc_hidden[b*H_ + h];
    } else {
        int tok = targets[(b*NS_ + slot)*L_ + (wi-1)];
        v = emb[(size_t)tok*H_ + h];
    }
    d_dec[(size_t)(wi*N_ + n)*H_ + h] = v;
}

// ---------------- fp32 SIMT GEMM 128x128 (gi GEMM, once) ----------------
__global__ void k_gemm_abt(const float* __restrict__ A, const float* __restrict__ Bm,
                           float* __restrict__ C, int M, int N,
                           const float* __restrict__ bias)
{
    __shared__ alignas(16) float As[8][128];
    __shared__ alignas(16) float Bs[8][128];
    const int tid = threadIdx.x;
    const int m0 = blockIdx.y * 128;
    const int n0 = blockIdx.x * 128;
    const int tm = (tid & 15) * 8;
    const int tn = (tid >> 4) * 8;

    float acc[8][8];
    #pragma unroll
    for (int i = 0; i < 8; i++)
        #pragma unroll
        for (int j = 0; j < 8; j++) acc[i][j] = 0.f;

    const int lr = tid >> 1;
    const int lk = (tid & 1) * 4;

    for (int k0 = 0; k0 < KDIM; k0 += 8) {
        float4 av = make_float4(0.f,0.f,0.f,0.f);
        float4 bv = make_float4(0.f,0.f,0.f,0.f);
        if (m0 + lr < M) av = *reinterpret_cast<const float4*>(A + (size_t)(m0+lr)*KDIM + k0 + lk);
        if (n0 + lr < N) bv = *reinterpret_cast<const float4*>(Bm + (size_t)(n0+lr)*KDIM + k0 + lk);
        __syncthreads();
        As[lk+0][lr]=av.x; As[lk+1][lr]=av.y; As[lk+2][lr]=av.z; As[lk+3][lr]=av.w;
        Bs[lk+0][lr]=bv.x; Bs[lk+1][lr]=bv.y; Bs[lk+2][lr]=bv.z; Bs[lk+3][lr]=bv.w;
        __syncthreads();
        #pragma unroll
        for (int kk = 0; kk < 8; kk++) {
            float4 a0 = *reinterpret_cast<float4*>(&As[kk][tm]);
            float4 a1 = *reinterpret_cast<float4*>(&As[kk][tm+4]);
            float4 b0 = *reinterpret_cast<float4*>(&Bs[kk][tn]);
            float4 b1 = *reinterpret_cast<float4*>(&Bs[kk][tn+4]);
            float a[8] = {a0.x,a0.y,a0.z,a0.w,a1.x,a1.y,a1.z,a1.w};
            float b[8] = {b0.x,b0.y,b0.z,b0.w,b1.x,b1.y,b1.z,b1.w};
            #pragma unroll
            for (int i = 0; i < 8; i++)
                #pragma unroll
                for (int j = 0; j < 8; j++)
                    acc[i][j] += a[i] * b[j];
        }
    }
    #pragma unroll
    for (int i = 0; i < 8; i++) {
        int m = m0 + tm + i;
        if (m < M) {
            #pragma unroll
            for (int j = 0; j < 8; j++) {
                int n = n0 + tn + j;
                if (n < N) {
                    float v = acc[i][j];
                    if (bias) v += bias[n];
                    C[(size_t)m*N + n] = v;
                }
            }
        }
    }
}

// ---------------- split-K gh GEMM (register-pipelined) ----------------
__global__ void __launch_bounds__(256) k_gemm_gh(const float* __restrict__ A,
                                                 const float* __restrict__ Bm)
{
    __shared__ alignas(16) float As[16][64];
    __shared__ alignas(16) float Bs[16][64];
    const int tid = threadIdx.x;
    const int m0 = blockIdx.y * 64;
    const int n0 = blockIdx.x * 64;
    const int s  = blockIdx.z;
    const int kbeg = s * KSEG;
    float* Cp = d_ghp[s];

    const int tm = (tid & 15) * 4;
    const int tn = (tid >> 4) * 4;
    const int lr = tid >> 2;
    const int lk = (tid & 3) * 4;
    const bool am = (m0 + lr < N_);
    const bool bn = (n0 + lr < H3_);

    float acc[4][4];
    #pragma unroll
    for (int i = 0; i < 4; i++)
        #pragma unroll
        for (int j = 0; j < 4; j++) acc[i][j] = 0.f;

    float4 ra = make_float4(0.f,0.f,0.f,0.f);
    float4 rb = make_float4(0.f,0.f,0.f,0.f);
    if (am) ra = *(const float4*)(A  + (size_t)(m0+lr)*KDIM + kbeg + lk);
    if (bn) rb = *(const float4*)(Bm + (size_t)(n0+lr)*KDIM + kbeg + lk);

    #pragma unroll 1
    for (int c = 0; c < KSEG/16; c++) {
        As[lk+0][lr]=ra.x; As[lk+1][lr]=ra.y; As[lk+2][lr]=ra.z; As[lk+3][lr]=ra.w;
        Bs[lk+0][lr]=rb.x; Bs[lk+1][lr]=rb.y; Bs[lk+2][lr]=rb.z; Bs[lk+3][lr]=rb.w;
        __syncthreads();
        if (c + 1 < KSEG/16) {
            int k0 = kbeg + (c + 1) * 16;
            if (am) ra = *(const float4*)(A  + (size_t)(m0+lr)*KDIM + k0 + lk);
            if (bn) rb = *(const float4*)(Bm + (size_t)(n0+lr)*KDIM + k0 + lk);
        }
        #pragma unroll
        for (int kk = 0; kk < 16; kk++) {
            float4 a4 = *(float4*)&As[kk][tm];
            float4 b4 = *(float4*)&Bs[kk][tn];
            float a[4] = {a4.x, a4.y, a4.z, a4.w};
            float b[4] = {b4.x, b4.y, b4.z, b4.w};
            #pragma unroll
            for (int i = 0; i < 4; i++)
                #pragma unroll
                for (int j = 0; j < 4; j++)
                    acc[i][j] += a[i] * b[j];
        }
        __syncthreads();
    }
    #pragma unroll
    for (int i = 0; i < 4; i++) {
        int m = m0 + tm + i;
        if (m < N_) {
            #pragma unroll
            for (int j = 0; j < 4; j++) {
                int n = n0 + tn + j;
                if (n < H3_) Cp[(size_t)m*H3_ + n] = acc[i][j];
            }
        }
    }
}

// ---------------- GRU combine ----------------
__global__ void k_gru(int wi, int pin, int pout, const float* __restrict__ b_hh)
{
    int n = blockIdx.x;
    int h = threadIdx.x;
    const float* gi = &d_gi[(size_t)(wi*N_ + n)*H3_];
    size_t base = (size_t)n*H3_;
    float g0 = b_hh[h], g1 = b_hh[H_+h], g2 = b_hh[2*H_+h];
    #pragma unroll
    for (int s = 0; s < KSPL; s++) {
        g0 += d_ghp[s][base + h];
        g1 += d_ghp[s][base + H_ + h];
        g2 += d_ghp[s][base + 2*H_ + h];
    }
    float hp = d_h[pin][n*H_ + h];
    float r  = 1.f / (1.f + expf(-(gi[h]      + g0)));
    float z  = 1.f / (1.f + expf(-(gi[H_+h]   + g1)));
    float nn = tanhf(gi[2*H_+h] + r * g2);
    float hv = (1.f - z) * nn + z * hp;
    d_h[pout][n*H_ + h] = hv;
    d_h_bf[n*KP + h] = __float2bfloat16(hv);
    if (h == 0) d_rowsum[n] = 0.f;
}

// ---------------- slot-grouped attention scores ----------------
__global__ void __launch_bounds__(256) k_scores_g(const float* __restrict__ enc,
                                                  const int* __restrict__ lens, int pcur)
{
    __shared__ alignas(16) float hsh[10][H_];
    const int b  = blockIdx.x;
    const int s0 = blockIdx.y * 10;
    const int t  = threadIdx.x;

    for (int i = t; i < 10 * H_; i += 256) {
        int s = i / H_, j = i % H_;
        hsh[s][j] = d_h[pcur][((s0 + s) * B_ + b) * H_ + j];
    }
    __syncthreads();

    float acc[10];
    #pragma unroll
    for (int s = 0; s < 10; s++) acc[s] = 0.f;
    const float4* e4 = (const float4*)(enc + ((size_t)b * T_ + t) * H_);
    for (int i = 0; i < H_ / 4; i++) {
        float4 e = e4[i];
        #pragma unroll
        for (int s = 0; s < 10; s++) {
            float4 h = ((const float4*)hsh[s])[i];
            acc[s] += e.x*h.x + e.y*h.y + e.z*h.z + e.w*h.w;
        }
    }
    int len = lens[b];
    #pragma unroll
    for (int s = 0; s < 10; s++)
        d_prob[((s0 + s) * B_ + b) * T_ + t] = (t < len) ? acc[s] : -1e9f;
}

// ---------------- softmax over T ----------------
__global__ void k_softmax_t()
{
    int n = blockIdx.x, t = threadIdx.x;
    __shared__ float red[8];
    int w = t >> 5, ln = t & 31;
    float v = d_prob[n*T_ + t];
    float m = v;
    #pragma unroll
    for (int o = 16; o > 0; o >>= 1) m = fmaxf(m, __shfl_xor_sync(0xffffffffu, m, o));
    if (ln == 0) red[w] = m;
    __syncthreads();
    float mx = red[0];
    #pragma unroll
    for (int i = 1; i < 8; i++) mx = fmaxf(mx, red[i]);
    __syncthreads();
    float e = expf(v - mx);
    float s = e;
    #pragma unroll
    for (int o = 16; o > 0; o >>= 1) s += __shfl_xor_sync(0xffffffffu, s, o);
    if (ln == 0) red[w] = s;
    __syncthreads();
    float sum = 0.f;
    #pragma unroll
    for (int i = 0; i < 8; i++) sum += red[i];
    d_prob[n*T_ + t] = e / sum;
}

// ---------------- batch-grouped context (partials over t-quarters) ----------
__global__ void __launch_bounds__(400) k_ctx_g(const float* __restrict__ enc)
{
    __shared__ float psh[30][64];
    const int b  = blockIdx.x;
    const int q  = blockIdx.y;
    const int t0 = q * 64;
    const int h  = threadIdx.x;

    for (int i = h; i < 30 * 64; i += 400) {
        int s = i >> 6, tt = i & 63;
        psh[s][tt] = d_prob[(s * B_ + b) * T_ + t0 + tt];
    }
    __syncthreads();

    float acc[30];
    #pragma unroll
    for (int s = 0; s < 30; s++) acc[s] = 0.f;
    #pragma unroll 2
    for (int tt = 0; tt < 64; tt++) {
        float e = enc[((size_t)b * T_ + t0 + tt) * H_ + h];
        #pragma unroll
        for (int s = 0; s < 30; s++) acc[s] += psh[s][tt] * e;
    }
    #pragma unroll
    for (int s = 0; s < 30; s++)
        d_ctxp[q][(s * B_ + b) * H_ + h] = acc[s];
}

// ---------------- switch (+ gates at step 0) ----------------
__device__ __forceinline__ float reduce128(float v, float* sm)
{
    #pragma unroll
    for (int o = 16; o > 0; o >>= 1) v += __shfl_xor_sync(0xffffffffu, v, o);
    int w = threadIdx.x >> 5, ln = threadIdx.x & 31;
    if (ln == 0) sm[w] = v;
    __syncthreads();
    float r = sm[0] + sm[1] + sm[2] + sm[3];
    __syncthreads();
    return r;
}

__global__ void k_switch(int wi, int pcur,
                         const float* __restrict__ w_ratio, const float* __restrict__ b_ratio,
                         const float* __restrict__ w_gate,  const float* __restrict__ b_gate,
                         float* __restrict__ out)
{
    __shared__ float sm[4];
    int n = blockIdx.x, tid = threadIdx.x;
    const float* hn = &d_h[pcur][n*H_];
    const float* xx = &d_dec[(size_t)(wi*N_ + n)*H_];
    float p = 0.f;
    for (int j = tid; j < H_; j += 128) {
        float cx = d_ctxp[0][n*H_+j] + d_ctxp[1][n*H_+j] + d_ctxp[2][n*H_+j] + d_ctxp[3][n*H_+j];
        p += hn[j]*w_ratio[j] + cx*w_ratio[H_+j] + xx[j]*w_ratio[2*H_+j];
    }
    p = reduce128(p, sm);
    if (tid == 0) d_sw[n] = 1.f / (1.f + expf(-(p + b_ratio[0])));
    if (wi == 0) {
        for (int g = 0; g < G_; g++) {
            float q = 0.f;
            for (int j = tid; j < H_; j += 128) {
                float cx = d_ctxp[0][n*H_+j] + d_ctxp[1][n*H_+j] + d_ctxp[2][n*H_+j] + d_ctxp[3][n*H_+j];
                q += cx * w_gate[g*H_ + j];
            }
            q = reduce128(q, sm);
            if (tid == 0)
                out[(size_t)N_*L_*V_ + (size_t)n*G_ + g] = q + b_gate[g];
        }
    }
}

// ---------------- finalize vocab part (float4) ----------------
__global__ void k_finalize(int wi, float* __restrict__ out)
{
    int n = blockIdx.y;
    int v4 = blockIdx.x * 256 + threadIdx.x;
    if (v4 >= V_/4) return;
    float scale = d_sw[n] / d_rowsum[n];
    float4 L = *(const float4*)&d_logits[(size_t)n*V_ + v4*4];
    float4 o;
    o.x = scale * L.x; o.y = scale * L.y; o.z = scale * L.z; o.w = scale * L.w;
    *(float4*)&out[((size_t)n*L_ + wi)*V_ + v4*4] = o;
}

// ---------------- pointer scatter ----------------
__global__ void k_scatter(int wi, const int* __restrict__ story, float* __restrict__ out)
{
    int n = blockIdx.x, t = threadIdx.x;
    int b0 = n % B_;
    float pv = d_prob[n*T_ + t] * (1.f - d_sw[n]);
    int v = story[b0*T_ + t];
    atomicAdd(&out[((size_t)n*L_ + wi)*V_ + v], pv);
}

// ---------------- host launcher ----------------
extern "C" void kernel_launch(void* const* d_in, const int* in_sizes, int n_in,
                              void* d_out, int out_size)
{
    const float* enc_hidden = (const float*)d_in[0];
    const float* enc_out    = (const float*)d_in[1];
    const float* emb        = (const float*)d_in[2];
    const float* w_ih       = (const float*)d_in[3];
    const float* w_hh       = (const float*)d_in[4];
    const float* b_ih       = (const float*)d_in[5];
    const float* b_hh       = (const float*)d_in[6];
    const float* w_ratio    = (const float*)d_in[7];
    const float* b_ratio    = (const float*)d_in[8];
    const float* w_gate     = (const float*)d_in[9];
    const float* b_gate     = (const float*)d_in[10];
    const float* slot_emb   = (const float*)d_in[11];
    const int*   lens       = (const int*)d_in[12];
    const int*   story      = (const int*)d_in[13];
    const int*   targets    = (const int*)d_in[14];
    const int*   domain_idx = (const int*)d_in[15];
    const int*   slotname_idx = (const int*)d_in[16];
    float* out = (float*)d_out;

    float *p_dec, *p_gi, *p_h, *p_logits;
    cudaGetSymbolAddress((void**)&p_dec, d_dec);
    cudaGetSymbolAddress((void**)&p_gi, d_gi);
    cudaGetSymbolAddress((void**)&p_h, d_h);
    cudaGetSymbolAddress((void**)&p_logits, d_logits);

    // side stream + events for vocab-GEMM / attention overlap (host objects,
    // created once; captured graph work is identical on every call)
    static cudaStream_t s_aux = nullptr;
    static cudaEvent_t evFork = nullptr, evJoin = nullptr;
    if (!s_aux) {
        cudaStreamCreateWithFlags(&s_aux, cudaStreamNonBlocking);
        cudaEventCreateWithFlags(&evFork, cudaEventDisableTiming);
        cudaEventCreateWithFlags(&evJoin, cudaEventDisableTiming);
    }

    cudaFuncSetAttribute(k_vocab_mma, cudaFuncAttributeMaxDynamicSharedMemorySize, VSM_BYTES);

    k_cvt_emb<<<(int)(((size_t)V_*KP + 255)/256), 256>>>(emb);

    k_prep<<<dim3(N_, L_), H_>>>(enc_hidden, emb, slot_emb, domain_idx, slotname_idx, targets);

    k_gemm_abt<<<dim3((H3_ + 127)/128, (L_*N_ + 127)/128), 256>>>(
        p_dec, w_ih, p_gi, L_*N_, H3_, b_ih);

    for (int wi = 0; wi < L_; wi++) {
        int pin = wi & 1, pout = (wi + 1) & 1;
        float* hprev = p_h + (size_t)pin * N_ * H_;

        k_gemm_gh<<<dim3((H3_ + 63)/64, (N_ + 63)/64, KSPL), 256>>>(hprev, w_hh);

        k_gru<<<N_, H_>>>(wi, pin, pout, b_hh);

        // fork: vocab GEMM on aux stream, attention chain on main stream
        cudaEventRecord(evFork, 0);
        cudaStreamWaitEvent(s_aux, evFork, 0);
        k_vocab_mma<<<dim3((V_ + 127)/128, 4), 256, VSM_BYTES, s_aux>>>(p_logits);
        cudaEventRecord(evJoin, s_aux);

        k_scores_g<<<dim3(B_, 3), 256>>>(enc_out, lens, pout);
        k_softmax_t<<<N_, T_>>>();
        k_ctx_g<<<dim3(B_, 4), 400>>>(enc_out);
        k_switch<<<N_, 128>>>(wi, pout, w_ratio, b_ratio, w_gate, b_gate, out);

        // join: finalize needs logits+rowsum (aux) and sw (main)
        cudaStreamWaitEvent(0, evJoin, 0);
        k_finalize<<<dim3((V_/4 + 255)/256, N_), 256>>>(wi, out);
        k_scatter<<<N_, T_>>>(wi, story, out);
    }
}

// round 15
// speedup vs baseline: 2.3747x; 1.0785x over previous
#include <cuda_runtime.h>
#include <cuda_bf16.h>
#include <math.h>
#include <stdint.h>

#define B_   16
#define T_   256
#define V_   18000
#define NS_  30
#define L_   10
#define G_   3
#define H_   400
#define N_   480      // NS_*B_
#define H3_  1200
#define KDIM 400
#define KP   448      // K padded to 7*64 for bf16 MMA
#define NKC  7        // K chunks of 64
#define KSPL 5        // split-K factor for gh GEMM
#define KSEG 80

// ---------------- scratch ----------------
__device__ float d_dec[L_*N_*H_];
__device__ float d_gi[L_*N_*H3_];
__device__ float d_ghp[KSPL][N_*H3_];
__device__ float d_h[2][N_*H_];
__device__ float d_prob[N_*T_];
__device__ float d_ctxp[4][N_*H_];
__device__ float d_sw[N_];
__device__ float d_rowsum[2][N_];               // double-buffered
__device__ float d_logits[2][(size_t)N_*V_];    // double-buffered
__device__ __nv_bfloat16 d_emb_bf[(size_t)V_*KP];
__device__ __nv_bfloat16 d_h_bf[2][512*KP];     // double-buffered

// ---------------- emb -> padded bf16 ----------------
__global__ void k_cvt_emb(const float* __restrict__ emb)
{
    size_t i = (size_t)blockIdx.x * 256 + threadIdx.x;
    if (i >= (size_t)V_ * KP) return;
    int c = (int)(i % KP);
    int n = (int)(i / KP);
    float v = (c < H_) ? emb[(size_t)n * H_ + c] : 0.f;
    d_emb_bf[i] = __float2bfloat16(v);
}

// ---------------- zero rowsum buffer ----------------
__global__ void k_zero(int buf)
{
    d_rowsum[buf][threadIdx.x] = 0.f;
}

// ================= mma.sync + cp.async helpers =================
__device__ __forceinline__ void ldmat4(uint32_t* r, uint32_t addr)
{
    asm volatile("ldmatrix.sync.aligned.m8n8.x4.shared.b16 {%0,%1,%2,%3}, [%4];"
                 : "=r"(r[0]), "=r"(r[1]), "=r"(r[2]), "=r"(r[3]) : "r"(addr));
}
__device__ __forceinline__ void mma_bf16(float* d, const uint32_t* a, uint32_t b0, uint32_t b1)
{
    asm volatile(
        "mma.sync.aligned.m16n8k16.row.col.f32.bf16.bf16.f32 "
        "{%0,%1,%2,%3}, {%4,%5,%6,%7}, {%8,%9}, {%0,%1,%2,%3};"
        : "+f"(d[0]), "+f"(d[1]), "+f"(d[2]), "+f"(d[3])
        : "r"(a[0]), "r"(a[1]), "r"(a[2]), "r"(a[3]), "r"(b0), "r"(b1));
}
__device__ __forceinline__ void cpa16(uint32_t dst, const void* src)
{
    asm volatile("cp.async.ca.shared.global [%0], [%1], 16;" :: "r"(dst), "l"(src));
}
__device__ __forceinline__ void cpa16z(uint32_t dst, const void* src, int valid)
{
    asm volatile("cp.async.ca.shared.global [%0], [%1], 16, %2;"
                 :: "r"(dst), "l"(src), "r"(valid ? 16 : 0));
}
#define CP_COMMIT() asm volatile("cp.async.commit_group;" ::: "memory")
#define CP_WAIT0()  asm volatile("cp.async.wait_group 0;" ::: "memory")

// ---------------- vocab GEMM (mma.sync, cp.async pipelined) ----------
#define VSM_BYTES (65536 + 512)
__global__ void __launch_bounds__(256) k_vocab_mma(int buf)
{
    extern __shared__ uint8_t sm[];
    float* srow = (float*)(sm + 65536);
    float* logits = d_logits[buf];
    const __nv_bfloat16* hbf = d_h_bf[buf];
    const int tid  = threadIdx.x;
    const int lane = tid & 31;
    const int wid  = tid >> 5;
    const int wm   = (wid & 1) * 64;
    const int wn   = (wid >> 1) * 32;
    const int m0   = blockIdx.y * 128;
    const int n0   = blockIdx.x * 128;
    const uint32_t smBase = (uint32_t)__cvta_generic_to_shared(sm);

    float acc[4][4][4];
    #pragma unroll
    for (int i = 0; i < 4; i++)
        #pragma unroll
        for (int j = 0; j < 4; j++)
            #pragma unroll
            for (int q = 0; q < 4; q++) acc[i][j][q] = 0.f;

    const int lr = tid >> 3, lc = tid & 7;

    auto issue = [&](int kc, int bs) {
        uint32_t aDst = smBase + bs * 16384;
        uint32_t bDst = smBase + 32768 + bs * 16384;
        #pragma unroll
        for (int p = 0; p < 4; p++) {
            int r = lr + p * 32;
            uint32_t off = (uint32_t)(r * 128 + lc * 16);
            uint32_t sw = off ^ ((off >> 3) & 0x70);
            cpa16(aDst + sw, (const char*)hbf + ((size_t)(m0 + r) * KP + kc * 64) * 2 + lc * 16);
            int gn = n0 + r;
            cpa16z(bDst + sw, (const char*)d_emb_bf + ((size_t)(gn < V_ ? gn : 0) * KP + kc * 64) * 2 + lc * 16,
                   gn < V_);
        }
    };

    issue(0, 0); CP_COMMIT();
    for (int kc = 0; kc < NKC; kc++) {
        CP_WAIT0();
        __syncthreads();
        if (kc < NKC - 1) { issue(kc + 1, (kc + 1) & 1); CP_COMMIT(); }
        const uint32_t aBase = smBase + (kc & 1) * 16384;
        const uint32_t bBase = smBase + 32768 + (kc & 1) * 16384;
        #pragma unroll
        for (int ks = 0; ks < 4; ks++) {
            uint32_t af[4][4];
            #pragma unroll
            for (int mt = 0; mt < 4; mt++) {
                int row  = wm + mt * 16 + (lane & 7) + ((lane & 8) ? 8 : 0);
                int koff = ks * 32 + ((lane & 16) ? 16 : 0);
                uint32_t off = (uint32_t)(row * 128 + koff);
                ldmat4(af[mt], aBase + (off ^ ((off >> 3) & 0x70)));
            }
            uint32_t bfr[2][4];
            #pragma unroll
            for (int hh = 0; hh < 2; hh++) {
                int row  = wn + hh * 16 + (lane & 7) + ((lane & 16) ? 8 : 0);
                int koff = ks * 32 + ((lane & 8) ? 16 : 0);
                uint32_t off = (uint32_t)(row * 128 + koff);
                ldmat4(bfr[hh], bBase + (off ^ ((off >> 3) & 0x70)));
            }
            #pragma unroll
            for (int mt = 0; mt < 4; mt++)
                #pragma unroll
                for (int nt = 0; nt < 4; nt++)
                    mma_bf16(acc[mt][nt], af[mt],
                             bfr[nt >> 1][(nt & 1) * 2 + 0],
                             bfr[nt >> 1][(nt & 1) * 2 + 1]);
        }
    }

    if (tid < 128) srow[tid] = 0.f;
    __syncthreads();
    #pragma unroll
    for (int mt = 0; mt < 4; mt++) {
        int rlo = wm + mt * 16 + (lane >> 2);
        int rhi = rlo + 8;
        int gmlo = m0 + rlo, gmhi = m0 + rhi;
        float slo = 0.f, shi = 0.f;
        #pragma unroll
        for (int nt = 0; nt < 4; nt++) {
            int gcol = n0 + wn + nt * 8 + 2 * (lane & 3);
            if (gcol < V_) {
                if (gmlo < N_) {
                    float e0 = __expf(acc[mt][nt][0]);
                    float e1 = __expf(acc[mt][nt][1]);
                    *(float2*)&logits[(size_t)gmlo * V_ + gcol] = make_float2(e0, e1);
                    slo += e0 + e1;
                }
                if (gmhi < N_) {
                    float e2 = __expf(acc[mt][nt][2]);
                    float e3 = __expf(acc[mt][nt][3]);
                    *(float2*)&logits[(size_t)gmhi * V_ + gcol] = make_float2(e2, e3);
                    shi += e2 + e3;
                }
            }
        }
        slo += __shfl_xor_sync(0xffffffffu, slo, 1);
        slo += __shfl_xor_sync(0xffffffffu, slo, 2);
        shi += __shfl_xor_sync(0xffffffffu, shi, 1);
        shi += __shfl_xor_sync(0xffffffffu, shi, 2);
        if ((lane & 3) == 0) {
            if (gmlo < N_) atomicAdd(&srow[rlo], slo);
            if (gmhi < N_) atomicAdd(&srow[rhi], shi);
        }
    }
    __syncthreads();
    if (tid < 128 && m0 + tid < N_) atomicAdd(&d_rowsum[buf][m0 + tid], srow[tid]);
}

// ---------------- K0: build decoder inputs + h0 ----------------
__global__ void k_prep(const float* __restrict__ enc_hidden,
                       const float* __restrict__ emb,
                       const float* __restrict__ slot_emb,
                       const int*   __restrict__ domain_idx,
                       const int*   __restrict__ slotname_idx,
                       const int*   __restrict__ targets)
{
    int n  = blockIdx.x;
    int wi = blockIdx.y;
    int h  = threadIdx.x;
    int slot = n / B_, b = n % B_;
    float v;
    if (wi == 0) {
        v = slot_emb[domain_idx[slot]*H_ + h] + slot_emb[slotname_idx[slot]*H_ + h];
        d_h[0][n*H_ + h] = enc_hidden[b*H_ + h];
    } else {
        int tok = targets[(b*NS_ + slot)*L_ + (wi-1)];
        v = emb[(size_t)tok*H_ + h];
    }
    d_dec[(size_t)(wi*N_ + n)*H_ + h] = v;
}

// ---------------- fp32 SIMT GEMM 128x128 (gi GEMM, once) ----------------
__global__ void k_gemm_abt(const float* __restrict__ A, const float* __restrict__ Bm,
                           float* __restrict__ C, int M, int N,
                           const float* __restrict__ bias)
{
    __shared__ alignas(16) float As[8][128];
    __shared__ alignas(16) float Bs[8][128];
    const int tid = threadIdx.x;
    const int m0 = blockIdx.y * 128;
    const int n0 = blockIdx.x * 128;
    const int tm = (tid & 15) * 8;
    const int tn = (tid >> 4) * 8;

    float acc[8][8];
    #pragma unroll
    for (int i = 0; i < 8; i++)
        #pragma unroll
        for (int j = 0; j < 8; j++) acc[i][j] = 0.f;

    const int lr = tid >> 1;
    const int lk = (tid & 1) * 4;

    for (int k0 = 0; k0 < KDIM; k0 += 8) {
        float4 av = make_float4(0.f,0.f,0.f,0.f);
        float4 bv = make_float4(0.f,0.f,0.f,0.f);
        if (m0 + lr < M) av = *reinterpret_cast<const float4*>(A + (size_t)(m0+lr)*KDIM + k0 + lk);
        if (n0 + lr < N) bv = *reinterpret_cast<const float4*>(Bm + (size_t)(n0+lr)*KDIM + k0 + lk);
        __syncthreads();
        As[lk+0][lr]=av.x; As[lk+1][lr]=av.y; As[lk+2][lr]=av.z; As[lk+3][lr]=av.w;
        Bs[lk+0][lr]=bv.x; Bs[lk+1][lr]=bv.y; Bs[lk+2][lr]=bv.z; Bs[lk+3][lr]=bv.w;
        __syncthreads();
        #pragma unroll
        for (int kk = 0; kk < 8; kk++) {
            float4 a0 = *reinterpret_cast<float4*>(&As[kk][tm]);
            float4 a1 = *reinterpret_cast<float4*>(&As[kk][tm+4]);
            float4 b0 = *reinterpret_cast<float4*>(&Bs[kk][tn]);
            float4 b1 = *reinterpret_cast<float4*>(&Bs[kk][tn+4]);
            float a[8] = {a0.x,a0.y,a0.z,a0.w,a1.x,a1.y,a1.z,a1.w};
            float b[8] = {b0.x,b0.y,b0.z,b0.w,b1.x,b1.y,b1.z,b1.w};
            #pragma unroll
            for (int i = 0; i < 8; i++)
                #pragma unroll
                for (int j = 0; j < 8; j++)
                    acc[i][j] += a[i] * b[j];
        }
    }
    #pragma unroll
    for (int i = 0; i < 8; i++) {
        int m = m0 + tm + i;
        if (m < M) {
            #pragma unroll
            for (int j = 0; j < 8; j++) {
                int n = n0 + tn + j;
                if (n < N) {
                    float v = acc[i][j];
                    if (bias) v += bias[n];
                    C[(size_t)m*N + n] = v;
                }
            }
        }
    }
}

// ---------------- split-K gh GEMM ----------------
__global__ void __launch_bounds__(256) k_gemm_gh(const float* __restrict__ A,
                                                 const float* __restrict__ Bm)
{
    __shared__ alignas(16) float As[16][64];
    __shared__ alignas(16) float Bs[16][64];
    const int tid = threadIdx.x;
    const int m0 = blockIdx.y * 64;
    const int n0 = blockIdx.x * 64;
    const int s  = blockIdx.z;
    const int kbeg = s * KSEG;
    float* Cp = d_ghp[s];

    const int tm = (tid & 15) * 4;
    const int tn = (tid >> 4) * 4;

    float acc[4][4];
    #pragma unroll
    for (int i = 0; i < 4; i++)
        #pragma unroll
        for (int j = 0; j < 4; j++) acc[i][j] = 0.f;

    const int lr = tid >> 2;
    const int lk = (tid & 3) * 4;

    for (int k0 = kbeg; k0 < kbeg + KSEG; k0 += 16) {
        __syncthreads();
        {
            float4 v = make_float4(0.f,0.f,0.f,0.f);
            if (m0 + lr < N_) v = *(const float4*)(A + (size_t)(m0+lr)*KDIM + k0 + lk);
            As[lk+0][lr]=v.x; As[lk+1][lr]=v.y; As[lk+2][lr]=v.z; As[lk+3][lr]=v.w;
        }
        {
            float4 v = make_float4(0.f,0.f,0.f,0.f);
            if (n0 + lr < H3_) v = *(const float4*)(Bm + (size_t)(n0+lr)*KDIM + k0 + lk);
            Bs[lk+0][lr]=v.x; Bs[lk+1][lr]=v.y; Bs[lk+2][lr]=v.z; Bs[lk+3][lr]=v.w;
        }
        __syncthreads();
        #pragma unroll
        for (int kk = 0; kk < 16; kk++) {
            float4 a4 = *(float4*)&As[kk][tm];
            float4 b4 = *(float4*)&Bs[kk][tn];
            float a[4] = {a4.x, a4.y, a4.z, a4.w};
            float b[4] = {b4.x, b4.y, b4.z, b4.w};
            #pragma unroll
            for (int i = 0; i < 4; i++)
                #pragma unroll
                for (int j = 0; j < 4; j++)
                    acc[i][j] += a[i] * b[j];
        }
    }
    #pragma unroll
    for (int i = 0; i < 4; i++) {
        int m = m0 + tm + i;
        if (m < N_) {
            #pragma unroll
            for (int j = 0; j < 4; j++) {
                int n = n0 + tn + j;
                if (n < H3_) Cp[(size_t)m*H3_ + n] = acc[i][j];
            }
        }
    }
}

// ---------------- GRU combine ----------------
__global__ void k_gru(int wi, int pin, int pout, const float* __restrict__ b_hh)
{
    int n = blockIdx.x;
    int h = threadIdx.x;
    int buf = wi & 1;
    const float* gi = &d_gi[(size_t)(wi*N_ + n)*H3_];
    size_t base = (size_t)n*H3_;
    float g0 = b_hh[h], g1 = b_hh[H_+h], g2 = b_hh[2*H_+h];
    #pragma unroll
    for (int s = 0; s < KSPL; s++) {
        g0 += d_ghp[s][base + h];
        g1 += d_ghp[s][base + H_ + h];
        g2 += d_ghp[s][base + 2*H_ + h];
    }
    float hp = d_h[pin][n*H_ + h];
    float r  = 1.f / (1.f + expf(-(gi[h]      + g0)));
    float z  = 1.f / (1.f + expf(-(gi[H_+h]   + g1)));
    float nn = tanhf(gi[2*H_+h] + r * g2);
    float hv = (1.f - z) * nn + z * hp;
    d_h[pout][n*H_ + h] = hv;
    d_h_bf[buf][n*KP + h] = __float2bfloat16(hv);
}

// ---------------- fused scores + softmax ----------------
__global__ void __launch_bounds__(256) k_scores_sm(const float* __restrict__ enc,
                                                   const int* __restrict__ lens, int pcur)
{
    __shared__ alignas(16) float hsh[10][H_];
    __shared__ float red[10][8];
    const int b  = blockIdx.x;
    const int s0 = blockIdx.y * 10;
    const int t  = threadIdx.x;
    const int ln = t & 31, w = t >> 5;

    for (int i = t; i < 10 * H_; i += 256) {
        int s = i / H_, j = i % H_;
        hsh[s][j] = d_h[pcur][((s0 + s) * B_ + b) * H_ + j];
    }
    __syncthreads();

    float acc[10];
    #pragma unroll
    for (int s = 0; s < 10; s++) acc[s] = 0.f;
    const float4* e4 = (const float4*)(enc + ((size_t)b * T_ + t) * H_);
    for (int i = 0; i < H_ / 4; i++) {
        float4 e = e4[i];
        #pragma unroll
        for (int s = 0; s < 10; s++) {
            float4 h = ((const float4*)hsh[s])[i];
            acc[s] += e.x*h.x + e.y*h.y + e.z*h.z + e.w*h.w;
        }
    }
    int len = lens[b];
    bool valid = (t < len);
    #pragma unroll
    for (int s = 0; s < 10; s++) if (!valid) acc[s] = -1e9f;

    #pragma unroll
    for (int s = 0; s < 10; s++) {
        float m = acc[s];
        #pragma unroll
        for (int o = 16; o > 0; o >>= 1) m = fmaxf(m, __shfl_xor_sync(0xffffffffu, m, o));
        if (ln == 0) red[s][w] = m;
    }
    __syncthreads();
    float e[10];
    #pragma unroll
    for (int s = 0; s < 10; s++) {
        float mx = red[s][0];
        #pragma unroll
        for (int i = 1; i < 8; i++) mx = fmaxf(mx, red[s][i]);
        e[s] = expf(acc[s] - mx);
    }
    __syncthreads();
    #pragma unroll
    for (int s = 0; s < 10; s++) {
        float ss = e[s];
        #pragma unroll
        for (int o = 16; o > 0; o >>= 1) ss += __shfl_xor_sync(0xffffffffu, ss, o);
        if (ln == 0) red[s][w] = ss;
    }
    __syncthreads();
    #pragma unroll
    for (int s = 0; s < 10; s++) {
        float sum = 0.f;
        #pragma unroll
        for (int i = 0; i < 8; i++) sum += red[s][i];
        d_prob[((s0 + s) * B_ + b) * T_ + t] = e[s] / sum;
    }
}

// ---------------- batch-grouped context ----------------
__global__ void __launch_bounds__(400) k_ctx_g(const float* __restrict__ enc)
{
    __shared__ float psh[30][64];
    const int b  = blockIdx.x;
    const int q  = blockIdx.y;
    const int t0 = q * 64;
    const int h  = threadIdx.x;

    for (int i = h; i < 30 * 64; i += 400) {
        int s = i >> 6, tt = i & 63;
        psh[s][tt] = d_prob[(s * B_ + b) * T_ + t0 + tt];
    }
    __syncthreads();

    float acc[30];
    #pragma unroll
    for (int s = 0; s < 30; s++) acc[s] = 0.f;
    #pragma unroll 2
    for (int tt = 0; tt < 64; tt++) {
        float e = enc[((size_t)b * T_ + t0 + tt) * H_ + h];
        #pragma unroll
        for (int s = 0; s < 30; s++) acc[s] += psh[s][tt] * e;
    }
    #pragma unroll
    for (int s = 0; s < 30; s++)
        d_ctxp[q][(s * B_ + b) * H_ + h] = acc[s];
}

// ---------------- switch (+ gates at step 0) ----------------
__device__ __forceinline__ float reduce128(float v, float* sm)
{
    #pragma unroll
    for (int o = 16; o > 0; o >>= 1) v += __shfl_xor_sync(0xffffffffu, v, o);
    int w = threadIdx.x >> 5, ln = threadIdx.x & 31;
    if (ln == 0) sm[w] = v;
    __syncthreads();
    float r = sm[0] + sm[1] + sm[2] + sm[3];
    __syncthreads();
    return r;
}

__global__ void k_switch(int wi, int pcur,
                         const float* __restrict__ w_ratio, const float* __restrict__ b_ratio,
                         const float* __restrict__ w_gate,  const float* __restrict__ b_gate,
                         float* __restrict__ out)
{
    __shared__ float sm[4];
    int n = blockIdx.x, tid = threadIdx.x;
    const float* hn = &d_h[pcur][n*H_];
    const float* xx = &d_dec[(size_t)(wi*N_ + n)*H_];
    float p = 0.f;
    for (int j = tid; j < H_; j += 128) {
        float cx = d_ctxp[0][n*H_+j] + d_ctxp[1][n*H_+j] + d_ctxp[2][n*H_+j] + d_ctxp[3][n*H_+j];
        p += hn[j]*w_ratio[j] + cx*w_ratio[H_+j] + xx[j]*w_ratio[2*H_+j];
    }
    p = reduce128(p, sm);
    if (tid == 0) d_sw[n] = 1.f / (1.f + expf(-(p + b_ratio[0])));
    if (wi == 0) {
        for (int g = 0; g < G_; g++) {
            float q = 0.f;
            for (int j = tid; j < H_; j += 128) {
                float cx = d_ctxp[0][n*H_+j] + d_ctxp[1][n*H_+j] + d_ctxp[2][n*H_+j] + d_ctxp[3][n*H_+j];
                q += cx * w_gate[g*H_ + j];
            }
            q = reduce128(q, sm);
            if (tid == 0)
                out[(size_t)N_*L_*V_ + (size_t)n*G_ + g] = q + b_gate[g];
        }
    }
}

// ---------------- finalize vocab part (float4) ----------------
__global__ void k_finalize(int wi, float* __restrict__ out)
{
    int n = blockIdx.y;
    int v4 = blockIdx.x * 256 + threadIdx.x;
    if (v4 >= V_/4) return;
    int buf = wi & 1;
    float scale = d_sw[n] / d_rowsum[buf][n];
    float4 L = *(const float4*)&d_logits[buf][(size_t)n*V_ + v4*4];
    float4 o;
    o.x = scale * L.x; o.y = scale * L.y; o.z = scale * L.z; o.w = scale * L.w;
    *(float4*)&out[((size_t)n*L_ + wi)*V_ + v4*4] = o;
}

// ---------------- pointer scatter ----------------
__global__ void k_scatter(int wi, const int* __restrict__ story, float* __restrict__ out)
{
    int n = blockIdx.x, t = threadIdx.x;
    int b0 = n % B_;
    float pv = d_prob[n*T_ + t] * (1.f - d_sw[n]);
    int v = story[b0*T_ + t];
    atomicAdd(&out[((size_t)n*L_ + wi)*V_ + v], pv);
}

// ---------------- host launcher ----------------
extern "C" void kernel_launch(void* const* d_in, const int* in_sizes, int n_in,
                              void* d_out, int out_size)
{
    const float* enc_hidden = (const float*)d_in[0];
    const float* enc_out    = (const float*)d_in[1];
    const float* emb        = (const float*)d_in[2];
    const float* w_ih       = (const float*)d_in[3];
    const float* w_hh       = (const float*)d_in[4];
    const float* b_ih       = (const float*)d_in[5];
    const float* b_hh       = (const float*)d_in[6];
    const float* w_ratio    = (const float*)d_in[7];
    const float* b_ratio    = (const float*)d_in[8];
    const float* w_gate     = (const float*)d_in[9];
    const float* b_gate     = (const float*)d_in[10];
    const float* slot_emb   = (const float*)d_in[11];
    const int*   lens       = (const int*)d_in[12];
    const int*   story      = (const int*)d_in[13];
    const int*   targets    = (const int*)d_in[14];
    const int*   domain_idx = (const int*)d_in[15];
    const int*   slotname_idx = (const int*)d_in[16];
    float* out = (float*)d_out;

    float *p_dec, *p_gi, *p_h;
    cudaGetSymbolAddress((void**)&p_dec, d_dec);
    cudaGetSymbolAddress((void**)&p_gi, d_gi);
    cudaGetSymbolAddress((void**)&p_h, d_h);

    static cudaStream_t s_aux = nullptr;
    static cudaEvent_t evSetup = nullptr, evGru = nullptr, evVoc = nullptr,
                       evFin = nullptr, evAtt = nullptr;
    if (!s_aux) {
        cudaStreamCreateWithFlags(&s_aux, cudaStreamNonBlocking);
        cudaEventCreateWithFlags(&evSetup, cudaEventDisableTiming);
        cudaEventCreateWithFlags(&evGru,   cudaEventDisableTiming);
        cudaEventCreateWithFlags(&evVoc,   cudaEventDisableTiming);
        cudaEventCreateWithFlags(&evFin,   cudaEventDisableTiming);
        cudaEventCreateWithFlags(&evAtt,   cudaEventDisableTiming);
    }
    cudaFuncSetAttribute(k_vocab_mma, cudaFuncAttributeMaxDynamicSharedMemorySize, VSM_BYTES);

    // setup (main stream)
    k_cvt_emb<<<(int)(((size_t)V_*KP + 255)/256), 256>>>(emb);
    k_prep<<<dim3(N_, L_), H_>>>(enc_hidden, emb, slot_emb, domain_idx, slotname_idx, targets);
    k_gemm_abt<<<dim3((H3_ + 127)/128, (L_*N_ + 127)/128), 256>>>(
        p_dec, w_ih, p_gi, L_*N_, H3_, b_ih);
    cudaEventRecord(evSetup, 0);
    // prime events so first-iteration waits bind to completed setup work
    cudaEventRecord(evFin, 0);
    cudaEventRecord(evAtt, 0);

    // spine prologue on s_aux: gh(0) + gru(0)
    cudaStreamWaitEvent(s_aux, evSetup, 0);
    k_gemm_gh<<<dim3((H3_ + 63)/64, (N_ + 63)/64, KSPL), 256, 0, s_aux>>>(p_h /*h[0]*/, w_hh);
    k_gru<<<N_, H_, 0, s_aux>>>(0, 0, 1, b_hh);
    cudaEventRecord(evGru, s_aux);

    for (int wi = 0; wi < L_; wi++) {
        int pout = (wi + 1) & 1;
        int buf = wi & 1;

        // main binds gru(wi) before aux re-records evGru
        cudaStreamWaitEvent(0, evGru, 0);

        // aux: vocab(wi) then spine for wi+1
        cudaStreamWaitEvent(s_aux, evFin, 0);       // rowsum/logits[buf] freed by finalize(wi-1)
        k_zero<<<1, N_, 0, s_aux>>>(buf);
        k_vocab_mma<<<dim3((V_ + 127)/128, 4), 256, VSM_BYTES, s_aux>>>(buf);
        cudaEventRecord(evVoc, s_aux);
        if (wi < L_ - 1) {
            k_gemm_gh<<<dim3((H3_ + 63)/64, (N_ + 63)/64, KSPL), 256, 0, s_aux>>>(
                p_h + (size_t)pout * N_ * H_, w_hh);
            cudaStreamWaitEvent(s_aux, evAtt, 0);   // d_h[wi&1] readers (attention wi-1) done
            k_gru<<<N_, H_, 0, s_aux>>>(wi + 1, pout, wi & 1, b_hh);
            cudaEventRecord(evGru, s_aux);
        }

        // main: attention chain for step wi
        k_scores_sm<<<dim3(B_, 3), 256>>>(enc_out, lens, pout);
        k_ctx_g<<<dim3(B_, 4), 400>>>(enc_out);
        k_switch<<<N_, 128>>>(wi, pout, w_ratio, b_ratio, w_gate, b_gate, out);
        cudaEventRecord(evAtt, 0);

        // join vocab, emit outputs
        cudaStreamWaitEvent(0, evVoc, 0);
        k_finalize<<<dim3((V_/4 + 255)/256, N_), 256>>>(wi, out);
        cudaEventRecord(evFin, 0);
        k_scatter<<<N_, T_>>>(wi, story, out);
    }
}